// round 5
// baseline (speedup 1.0000x reference)
#include <cuda_runtime.h>
#include <cuda_bf16.h>
#include <cstdint>

#define NN 100000
#define EE 600000
#define GG 1000
#define GTILES 1563   // ceil(NN/64)
#define NB 391        // ceil(NN/256)

// ---------------- static device scratch --------------------------------------
__device__ float d_dinv[NN];
__device__ float d_g[(size_t)NN * 128];      // ping
__device__ float d_h[(size_t)NN * 128];      // pong
__device__ float d_pool[GG * 128];
__device__ float d_pcnt[GG];
__device__ int   d_cnti[NN];
__device__ int   d_off[NN + 1];
__device__ int   d_cur[NN];
__device__ int   d_csr[EE];
__device__ int   d_bsum[NB + 1];
__device__ __nv_bfloat16 d_whi[128 * 128];   // W^T bf16 high, [n][k]
__device__ __nv_bfloat16 d_wlo[128 * 128];   // W^T bf16 low

// ---------------- helpers ------------------------------------------------------
__device__ __forceinline__ uint32_t smem_u32(const void* p) {
    uint32_t a;
    asm("{ .reg .u64 t; cvta.to.shared.u64 t, %1; cvt.u32.u64 %0, t; }" : "=r"(a) : "l"(p));
    return a;
}
#define LDM_X4(r, addr) \
    asm volatile("ldmatrix.sync.aligned.m8n8.x4.shared.b16 {%0,%1,%2,%3}, [%4];" \
        : "=r"((r)[0]), "=r"((r)[1]), "=r"((r)[2]), "=r"((r)[3]) : "r"(addr))

__device__ __forceinline__ void mma_bf16(float* c, const uint32_t* a, const uint32_t* b) {
    asm volatile("mma.sync.aligned.m16n8k16.row.col.f32.bf16.bf16.f32 "
        "{%0,%1,%2,%3}, {%4,%5,%6,%7}, {%8,%9}, {%0,%1,%2,%3};"
        : "+f"(c[0]), "+f"(c[1]), "+f"(c[2]), "+f"(c[3])
        : "r"(a[0]), "r"(a[1]), "r"(a[2]), "r"(a[3]), "r"(b[0]), "r"(b[1]));
}

// CSR gather of one 128-float row (lane l owns float4 l), 2-way unrolled.
__device__ __forceinline__ float4 gather_row(const float4* __restrict__ P,
                                             int m, int l) {
    float4 a = __ldg(&P[(size_t)m * 32 + l]);
    int beg = __ldg(&d_off[m]), end = __ldg(&d_off[m + 1]);
    float4 a1 = make_float4(0.f, 0.f, 0.f, 0.f);
    int e = beg;
    for (; e + 1 < end; e += 2) {
        int s0 = __ldg(&d_csr[e]);
        int s1 = __ldg(&d_csr[e + 1]);
        float4 x0 = __ldg(&P[(size_t)s0 * 32 + l]);
        float4 x1 = __ldg(&P[(size_t)s1 * 32 + l]);
        a.x += x0.x; a.y += x0.y; a.z += x0.z; a.w += x0.w;
        a1.x += x1.x; a1.y += x1.y; a1.z += x1.z; a1.w += x1.w;
    }
    if (e < end) {
        int s0 = __ldg(&d_csr[e]);
        float4 x0 = __ldg(&P[(size_t)s0 * 32 + l]);
        a.x += x0.x; a.y += x0.y; a.z += x0.z; a.w += x0.w;
    }
    a.x += a1.x; a.y += a1.y; a.z += a1.z; a.w += a1.w;
    return a;
}

// ---------------- degree / CSR ------------------------------------------------
__global__ void k_zero_cnt() {
    int i = blockIdx.x * 256 + threadIdx.x;
    if (i < NN) d_cnti[i] = 0;
}
__global__ void k_count(const int* __restrict__ dst) {
    int e = blockIdx.x * 256 + threadIdx.x;
    if (e < EE) atomicAdd(&d_cnti[dst[e]], 1);
}
__global__ void k_dinv() {
    int i = blockIdx.x * 256 + threadIdx.x;
    if (i < NN) d_dinv[i] = rsqrtf((float)(d_cnti[i] + 1));
}
__global__ void k_scan1() {
    __shared__ int s[256];
    int b = blockIdx.x, t = threadIdx.x;
    int i = b * 256 + t;
    int v = (i < NN) ? d_cnti[i] : 0;
    s[t] = v;
    __syncthreads();
#pragma unroll
    for (int off = 1; off < 256; off <<= 1) {
        int x = (t >= off) ? s[t - off] : 0;
        __syncthreads();
        s[t] += x;
        __syncthreads();
    }
    if (i < NN) d_off[i] = s[t] - v;
    if (t == 255) d_bsum[b] = s[255];
}
__global__ void k_scan2() {   // 1 block, 512 threads
    __shared__ int s[512];
    int t = threadIdx.x;
    int v = (t < NB) ? d_bsum[t] : 0;
    s[t] = v;
    __syncthreads();
#pragma unroll
    for (int off = 1; off < 512; off <<= 1) {
        int x = (t >= off) ? s[t - off] : 0;
        __syncthreads();
        s[t] += x;
        __syncthreads();
    }
    if (t < NB) d_bsum[t] = s[t] - v;
}
__global__ void k_scan3() {
    int b = blockIdx.x, t = threadIdx.x;
    int i = b * 256 + t;
    if (i < NN) {
        int o = d_off[i] + d_bsum[b];
        d_off[i] = o;
        d_cur[i] = o;
    }
    if (i == 0) d_off[NN] = EE;
}
__global__ void k_fill(const int* __restrict__ src, const int* __restrict__ dst) {
    int e = blockIdx.x * 256 + threadIdx.x;
    if (e < EE) {
        int pos = atomicAdd(&d_cur[dst[e]], 1);
        d_csr[pos] = src[e];
    }
}

// ---------------- W -> bf16 hi/lo, transposed [n][k] --------------------------
__global__ void k_wconv(const float* __restrict__ W) {
    int idx = blockIdx.x * 256 + threadIdx.x;   // 64 x 256
    int n = idx & 127, k = idx >> 7;
    float wv = __ldg(&W[k * 128 + n]);
    __nv_bfloat16 hb = __float2bfloat16_rn(wv);
    __nv_bfloat16 lb = __float2bfloat16_rn(wv - __bfloat162float(hb));
    d_whi[n * 128 + k] = hb;
    d_wlo[n * 128 + k] = lb;
}

// ---------------- layer 0: p0 = dinv * (x @ W0), K=4 --------------------------
__global__ void k_gemm0(const float* __restrict__ x, const float* __restrict__ W0) {
    int t = threadIdx.x;
    int j = t & 31;
    float w[16];
#pragma unroll
    for (int k = 0; k < 4; k++)
#pragma unroll
        for (int c = 0; c < 4; c++)
            w[k * 4 + c] = __ldg(&W0[k * 128 + j * 4 + c]);
    int gw = blockIdx.x * 8 + (t >> 5);
    for (int n = gw; n < NN; n += gridDim.x * 8) {
        float4 xv = __ldg((const float4*)x + n);
        float di = d_dinv[n];
        float4 r;
        r.x = di * (xv.x * w[0] + xv.y * w[4] + xv.z * w[8]  + xv.w * w[12]);
        r.y = di * (xv.x * w[1] + xv.y * w[5] + xv.z * w[9]  + xv.w * w[13]);
        r.z = di * (xv.x * w[2] + xv.y * w[6] + xv.z * w[10] + xv.w * w[14]);
        r.w = di * (xv.x * w[3] + xv.y * w[7] + xv.z * w[11] + xv.w * w[15]);
        ((float4*)d_g)[(size_t)n * 32 + j] = r;
    }
}

// ---------------- fused gather + HMMA GEMM ------------------------------------
// out = dinv * ( relu(dinv * (p[v] + sum p[src]) + b) @ W )
// 64 rows x 128 cols per block, 256 threads.
#define PITCH 136
#define A_HI 0
#define A_LO 17408
#define B_HI 34816
#define B_LO 69632
#define SMEM_MMA 104448

__global__ void __launch_bounds__(256) k_gg(const float* __restrict__ in,
                                            const float* __restrict__ bias,
                                            float* __restrict__ out) {
    extern __shared__ char smb[];
    uint32_t sbase = smem_u32(smb);
    int t = threadIdx.x, w = t >> 5, l = t & 31;

    // ---- copy pre-converted W hi/lo into padded smem ----
    const uint4* WH = (const uint4*)d_whi;
    const uint4* WL = (const uint4*)d_wlo;
#pragma unroll
    for (int i = t; i < 2048; i += 256) {
        int n = i >> 4, k8 = (i & 15) * 8;
        int off = (n * PITCH + k8) * 2;
        *(uint4*)(smb + B_HI + off) = __ldg(&WH[i]);
        *(uint4*)(smb + B_LO + off) = __ldg(&WL[i]);
    }

    // ---- A tile: gather + bias + relu + bf16 split; warp w -> rows w*8..w*8+7
    int tile = blockIdx.x;
    const float4* P = (const float4*)in;
    float4 bb = __ldg((const float4*)bias + l);
#pragma unroll 1
    for (int i = 0; i < 8; i++) {
        int r = w * 8 + i;
        int m = tile * 64 + r;
        float a0 = 0.f, a1 = 0.f, a2 = 0.f, a3 = 0.f;
        if (m < NN) {
            float4 s = gather_row(P, m, l);
            float di = __ldg(&d_dinv[m]);
            a0 = fmaxf(fmaf(di, s.x, bb.x), 0.f);
            a1 = fmaxf(fmaf(di, s.y, bb.y), 0.f);
            a2 = fmaxf(fmaf(di, s.z, bb.z), 0.f);
            a3 = fmaxf(fmaf(di, s.w, bb.w), 0.f);
        }
        __nv_bfloat16 h0 = __float2bfloat16_rn(a0), h1 = __float2bfloat16_rn(a1);
        __nv_bfloat16 h2 = __float2bfloat16_rn(a2), h3 = __float2bfloat16_rn(a3);
        __nv_bfloat16 l0 = __float2bfloat16_rn(a0 - __bfloat162float(h0));
        __nv_bfloat16 l1 = __float2bfloat16_rn(a1 - __bfloat162float(h1));
        __nv_bfloat16 l2 = __float2bfloat16_rn(a2 - __bfloat162float(h2));
        __nv_bfloat16 l3 = __float2bfloat16_rn(a3 - __bfloat162float(h3));
        uint2 hp, lp;
        hp.x = (uint32_t)__bfloat16_as_ushort(h0) | ((uint32_t)__bfloat16_as_ushort(h1) << 16);
        hp.y = (uint32_t)__bfloat16_as_ushort(h2) | ((uint32_t)__bfloat16_as_ushort(h3) << 16);
        lp.x = (uint32_t)__bfloat16_as_ushort(l0) | ((uint32_t)__bfloat16_as_ushort(l1) << 16);
        lp.y = (uint32_t)__bfloat16_as_ushort(l2) | ((uint32_t)__bfloat16_as_ushort(l3) << 16);
        int off = (r * PITCH + l * 4) * 2;
        *(uint2*)(smb + A_HI + off) = hp;
        *(uint2*)(smb + A_LO + off) = lp;
    }
    __syncthreads();

    // ---- fragment addresses ----
    int rs = (w >> 1) * 16;
    int cb = (w & 1) * 64;
    int arow = rs + (l & 7) + ((l >> 3) & 1) * 8;
    int acol8 = (l >> 4) * 8;
    uint32_t a_hi = sbase + A_HI + (arow * PITCH + acol8) * 2;
    uint32_t a_lo = sbase + A_LO + (arow * PITCH + acol8) * 2;
    int brow = (l & 7) + (l >> 4) * 8;
    int bk8  = ((l >> 3) & 1) * 8;

    float acc[32];
#pragma unroll
    for (int i = 0; i < 32; i++) acc[i] = 0.f;

#pragma unroll
    for (int kb = 0; kb < 8; kb++) {
        int k0 = kb * 16;
        uint32_t ah[4], al[4];
        LDM_X4(ah, a_hi + k0 * 2);
        LDM_X4(al, a_lo + k0 * 2);
#pragma unroll
        for (int np = 0; np < 4; np++) {
            int nb = cb + np * 16;
            uint32_t boff = (uint32_t)(((nb + brow) * PITCH + k0 + bk8) * 2);
            uint32_t bh[4], bl[4];
            LDM_X4(bh, sbase + B_HI + boff);
            LDM_X4(bl, sbase + B_LO + boff);
            float* c = acc + np * 8;
            mma_bf16(c,     ah, bh);
            mma_bf16(c,     ah, bl);
            mma_bf16(c,     al, bh);
            mma_bf16(c + 4, ah, bh + 2);
            mma_bf16(c + 4, ah, bl + 2);
            mma_bf16(c + 4, al, bh + 2);
        }
    }

    // ---- epilogue: scale rows by dinv, store fp32 ----
    int r0 = tile * 64 + rs + (l >> 2);
    int r1 = r0 + 8;
    float d0 = (r0 < NN) ? d_dinv[r0] : 0.f;
    float d1 = (r1 < NN) ? d_dinv[r1] : 0.f;
#pragma unroll
    for (int nt = 0; nt < 8; nt++) {
        int col = cb + nt * 8 + (l & 3) * 2;
        float* a = acc + nt * 4;
        if (r0 < NN) *(float2*)&out[(size_t)r0 * 128 + col] = make_float2(a[0] * d0, a[1] * d0);
        if (r1 < NN) *(float2*)&out[(size_t)r1 * 128 + col] = make_float2(a[2] * d1, a[3] * d1);
    }
}

// ---------------- fused gather + pooling --------------------------------------
__global__ void k_zero_pool() {
    int i = blockIdx.x * 256 + threadIdx.x;
    if (i < GG * 128) d_pool[i] = 0.f;
    if (i < GG) d_pcnt[i] = 0.f;
}
__global__ void k_gpool(const float* __restrict__ in, const int* __restrict__ batch,
                        const float* __restrict__ b3) {
    int v = blockIdx.x * 8 + (threadIdx.x >> 5);   // grid NN/8 exact
    int l = threadIdx.x & 31;
    const float4* P = (const float4*)in;
    float4 s = gather_row(P, v, l);
    float di = __ldg(&d_dinv[v]);
    float4 bb = __ldg((const float4*)b3 + l);
    float4 o;
    o.x = fmaxf(fmaf(di, s.x, bb.x), 0.f);
    o.y = fmaxf(fmaf(di, s.y, bb.y), 0.f);
    o.z = fmaxf(fmaf(di, s.z, bb.z), 0.f);
    o.w = fmaxf(fmaf(di, s.w, bb.w), 0.f);
    int g = __ldg(&batch[v]);
    float* p = d_pool + g * 128 + l * 4;
    asm volatile("red.global.add.v4.f32 [%0], {%1,%2,%3,%4};"
                 :: "l"(p), "f"(o.x), "f"(o.y), "f"(o.z), "f"(o.w) : "memory");
    if (l == 0) atomicAdd(&d_pcnt[g], 1.0f);
}

// ---------------- final MLP ----------------------------------------------------
__global__ void k_mlp(const float* __restrict__ xs, const float* __restrict__ Wl1,
                      const float* __restrict__ bl1, const float* __restrict__ Wl2,
                      const float* __restrict__ bl2, float* __restrict__ out) {
    __shared__ float feat[132];
    __shared__ float part[64];
    int g = blockIdx.x, t = threadIdx.x;
    float inv = 1.0f / fmaxf(d_pcnt[g], 1.0f);
    for (int i = t; i < 132; i += 64)
        feat[i] = (i < 128) ? d_pool[g * 128 + i] * inv : xs[g * 4 + (i - 128)];
    __syncthreads();
    float h = bl1[t];
#pragma unroll 4
    for (int i = 0; i < 132; i++) h = fmaf(feat[i], Wl1[i * 64 + t], h);
    h = fmaxf(h, 0.f);
    part[t] = h * Wl2[t];
    __syncthreads();
    if (t == 0) {
        float s = bl2[0];
#pragma unroll
        for (int j = 0; j < 64; j++) s += part[j];
        out[g] = s;
    }
}

// ---------------- launcher ----------------------------------------------------
extern "C" void kernel_launch(void* const* d_in, const int* in_sizes, int n_in,
                              void* d_out, int out_size) {
    const float* x     = (const float*)d_in[0];
    const int*   ei    = (const int*)d_in[1];
    const float* xs    = (const float*)d_in[2];
    const int*   batch = (const int*)d_in[3];
    const float* W0  = (const float*)d_in[4];
    const float* b0  = (const float*)d_in[5];
    const float* W1  = (const float*)d_in[6];
    const float* b1  = (const float*)d_in[7];
    const float* W2  = (const float*)d_in[8];
    const float* b2  = (const float*)d_in[9];
    const float* W3  = (const float*)d_in[10];
    const float* b3  = (const float*)d_in[11];
    const float* Wl1 = (const float*)d_in[12];
    const float* bl1 = (const float*)d_in[13];
    const float* Wl2 = (const float*)d_in[14];
    const float* bl2 = (const float*)d_in[15];
    float* out = (float*)d_out;

    const int* srcp = ei;
    const int* dstp = ei + EE;

    cudaFuncSetAttribute(k_gg, cudaFuncAttributeMaxDynamicSharedMemorySize, SMEM_MMA);

    float *gp, *hp;
    cudaGetSymbolAddress((void**)&gp, d_g);
    cudaGetSymbolAddress((void**)&hp, d_h);

    // degree + CSR build (reused by all 4 layers)
    k_zero_cnt<<<NB, 256>>>();
    k_count<<<(EE + 255) / 256, 256>>>(dstp);
    k_dinv<<<NB, 256>>>();
    k_scan1<<<NB, 256>>>();
    k_scan2<<<1, 512>>>();
    k_scan3<<<NB, 256>>>();
    k_fill<<<(EE + 255) / 256, 256>>>(srcp, dstp);

    // layer 0: p0 -> d_g
    k_gemm0<<<1024, 256>>>(x, W0);

    // layers 1..3: fused gather + GEMM, ping-pong d_g <-> d_h
    k_wconv<<<64, 256>>>(W1);
    k_gg<<<GTILES, 256, SMEM_MMA>>>(gp, b0, hp);

    k_wconv<<<64, 256>>>(W2);
    k_gg<<<GTILES, 256, SMEM_MMA>>>(hp, b1, gp);

    k_wconv<<<64, 256>>>(W3);
    k_gg<<<GTILES, 256, SMEM_MMA>>>(gp, b2, hp);

    // fused gather + pool + head
    k_zero_pool<<<(GG * 128 + 255) / 256, 256>>>();
    k_gpool<<<NN / 8, 256>>>(hp, batch, b3);
    k_mlp<<<GG, 64>>>(xs, Wl1, bl1, Wl2, bl2, out);
}

// round 6
// speedup vs baseline: 1.2919x; 1.2919x over previous
#include <cuda_runtime.h>
#include <cuda_bf16.h>
#include <cstdint>

#define NN 100000
#define EE 600000
#define GG 1000
#define GT128 782    // ceil(NN/128)
#define NB 391       // ceil(NN/256)

// ---------------- static device scratch --------------------------------------
__device__ float d_dinv[NN];
__device__ float d_g[(size_t)NN * 128];      // ping
__device__ float d_h[(size_t)NN * 128];      // pong
__device__ float d_acc[(size_t)NN * 128];    // gather staging
__device__ float d_pool[GG * 128];
__device__ float d_pcnt[GG];
__device__ int   d_cnti[NN];
__device__ int   d_off[NN + 1];
__device__ int   d_cur[NN];
__device__ int   d_csr[EE];
__device__ int   d_bsum[NB + 1];
__device__ __nv_bfloat16 d_whi[128 * 128];   // W^T bf16 high, [n][k]
__device__ __nv_bfloat16 d_wlo[128 * 128];   // W^T bf16 low

// ---------------- helpers ------------------------------------------------------
__device__ __forceinline__ uint32_t smem_u32(const void* p) {
    uint32_t a;
    asm("{ .reg .u64 t; cvta.to.shared.u64 t, %1; cvt.u32.u64 %0, t; }" : "=r"(a) : "l"(p));
    return a;
}
#define LDM_X4(r, addr) \
    asm volatile("ldmatrix.sync.aligned.m8n8.x4.shared.b16 {%0,%1,%2,%3}, [%4];" \
        : "=r"((r)[0]), "=r"((r)[1]), "=r"((r)[2]), "=r"((r)[3]) : "r"(addr))

__device__ __forceinline__ void mma_bf16(float* c, const uint32_t* a, const uint32_t* b) {
    asm volatile("mma.sync.aligned.m16n8k16.row.col.f32.bf16.bf16.f32 "
        "{%0,%1,%2,%3}, {%4,%5,%6,%7}, {%8,%9}, {%0,%1,%2,%3};"
        : "+f"(c[0]), "+f"(c[1]), "+f"(c[2]), "+f"(c[3])
        : "r"(a[0]), "r"(a[1]), "r"(a[2]), "r"(a[3]), "r"(b[0]), "r"(b[1]));
}

// CSR gather of one 128-float row (lane l owns float4 l), 2-way unrolled.
__device__ __forceinline__ float4 gather_row(const float4* __restrict__ P,
                                             int m, int l) {
    float4 a = __ldg(&P[(size_t)m * 32 + l]);
    int beg = __ldg(&d_off[m]), end = __ldg(&d_off[m + 1]);
    float4 a1 = make_float4(0.f, 0.f, 0.f, 0.f);
    int e = beg;
    for (; e + 1 < end; e += 2) {
        int s0 = __ldg(&d_csr[e]);
        int s1 = __ldg(&d_csr[e + 1]);
        float4 x0 = __ldg(&P[(size_t)s0 * 32 + l]);
        float4 x1 = __ldg(&P[(size_t)s1 * 32 + l]);
        a.x += x0.x; a.y += x0.y; a.z += x0.z; a.w += x0.w;
        a1.x += x1.x; a1.y += x1.y; a1.z += x1.z; a1.w += x1.w;
    }
    if (e < end) {
        int s0 = __ldg(&d_csr[e]);
        float4 x0 = __ldg(&P[(size_t)s0 * 32 + l]);
        a.x += x0.x; a.y += x0.y; a.z += x0.z; a.w += x0.w;
    }
    a.x += a1.x; a.y += a1.y; a.z += a1.z; a.w += a1.w;
    return a;
}

// ---------------- degree / CSR ------------------------------------------------
__global__ void k_zero_cnt() {
    int i = blockIdx.x * 256 + threadIdx.x;
    if (i < NN) d_cnti[i] = 0;
}
__global__ void k_count(const int* __restrict__ dst) {
    int e = blockIdx.x * 256 + threadIdx.x;
    if (e < EE) atomicAdd(&d_cnti[dst[e]], 1);
}
__global__ void k_dinv() {
    int i = blockIdx.x * 256 + threadIdx.x;
    if (i < NN) d_dinv[i] = rsqrtf((float)(d_cnti[i] + 1));
}
__global__ void k_scan1() {
    __shared__ int s[256];
    int b = blockIdx.x, t = threadIdx.x;
    int i = b * 256 + t;
    int v = (i < NN) ? d_cnti[i] : 0;
    s[t] = v;
    __syncthreads();
#pragma unroll
    for (int off = 1; off < 256; off <<= 1) {
        int x = (t >= off) ? s[t - off] : 0;
        __syncthreads();
        s[t] += x;
        __syncthreads();
    }
    if (i < NN) d_off[i] = s[t] - v;
    if (t == 255) d_bsum[b] = s[255];
}
__global__ void k_scan2() {   // 1 block, 512 threads
    __shared__ int s[512];
    int t = threadIdx.x;
    int v = (t < NB) ? d_bsum[t] : 0;
    s[t] = v;
    __syncthreads();
#pragma unroll
    for (int off = 1; off < 512; off <<= 1) {
        int x = (t >= off) ? s[t - off] : 0;
        __syncthreads();
        s[t] += x;
        __syncthreads();
    }
    if (t < NB) d_bsum[t] = s[t] - v;
}
__global__ void k_scan3() {
    int b = blockIdx.x, t = threadIdx.x;
    int i = b * 256 + t;
    if (i < NN) {
        int o = d_off[i] + d_bsum[b];
        d_off[i] = o;
        d_cur[i] = o;
    }
    if (i == 0) d_off[NN] = EE;
}
__global__ void k_fill(const int* __restrict__ src, const int* __restrict__ dst) {
    int e = blockIdx.x * 256 + threadIdx.x;
    if (e < EE) {
        int pos = atomicAdd(&d_cur[dst[e]], 1);
        d_csr[pos] = src[e];
    }
}

// ---------------- W -> bf16 hi/lo, transposed [n][k] --------------------------
__global__ void k_wconv(const float* __restrict__ W) {
    int idx = blockIdx.x * 256 + threadIdx.x;   // 64 x 256
    int n = idx & 127, k = idx >> 7;
    float wv = __ldg(&W[k * 128 + n]);
    __nv_bfloat16 hb = __float2bfloat16_rn(wv);
    __nv_bfloat16 lb = __float2bfloat16_rn(wv - __bfloat162float(hb));
    d_whi[n * 128 + k] = hb;
    d_wlo[n * 128 + k] = lb;
}

// ---------------- layer 0: p0 = dinv * (x @ W0), K=4 --------------------------
__global__ void k_gemm0(const float* __restrict__ x, const float* __restrict__ W0) {
    int t = threadIdx.x;
    int j = t & 31;
    float w[16];
#pragma unroll
    for (int k = 0; k < 4; k++)
#pragma unroll
        for (int c = 0; c < 4; c++)
            w[k * 4 + c] = __ldg(&W0[k * 128 + j * 4 + c]);
    int gw = blockIdx.x * 8 + (t >> 5);
    for (int n = gw; n < NN; n += gridDim.x * 8) {
        float4 xv = __ldg((const float4*)x + n);
        float di = d_dinv[n];
        float4 r;
        r.x = di * (xv.x * w[0] + xv.y * w[4] + xv.z * w[8]  + xv.w * w[12]);
        r.y = di * (xv.x * w[1] + xv.y * w[5] + xv.z * w[9]  + xv.w * w[13]);
        r.z = di * (xv.x * w[2] + xv.y * w[6] + xv.z * w[10] + xv.w * w[14]);
        r.w = di * (xv.x * w[3] + xv.y * w[7] + xv.z * w[11] + xv.w * w[15]);
        ((float4*)d_g)[(size_t)n * 32 + j] = r;
    }
}

// ---------------- standalone CSR gather: acc[v] = p[v] + sum p[src] -----------
__global__ void k_gather(const float* __restrict__ in) {   // grid NN/8, block 256
    int v = blockIdx.x * 8 + (threadIdx.x >> 5);
    int l = threadIdx.x & 31;
    float4 a = gather_row((const float4*)in, v, l);
    ((float4*)d_acc)[(size_t)v * 32 + l] = a;
}

// ---------------- HMMA GEMM: p = dinv * (relu(dinv*s + b) @ W) ----------------
// 128 rows x 128 cols per block, 512 threads (16 warps = 8 row-strips x 2 halves).
#define PITCH 136
#define A_HI 0
#define A_LO 34816
#define B_HI 69632
#define B_LO 104448
#define SMEM_MMA 139264

__global__ void __launch_bounds__(512) k_gemm_mma(const float* __restrict__ in,
                                                  const float* __restrict__ bias,
                                                  float* __restrict__ out) {
    extern __shared__ char smb[];
    uint32_t sbase = smem_u32(smb);
    int t = threadIdx.x, w = t >> 5, l = t & 31;

    // ---- copy pre-converted W hi/lo into padded smem ----
    const uint4* WH = (const uint4*)d_whi;
    const uint4* WL = (const uint4*)d_wlo;
#pragma unroll
    for (int i = t; i < 2048; i += 512) {
        int n = i >> 4, k8 = (i & 15) * 8;
        int off = (n * PITCH + k8) * 2;
        *(uint4*)(smb + B_HI + off) = __ldg(&WH[i]);
        *(uint4*)(smb + B_LO + off) = __ldg(&WL[i]);
    }

    // ---- A tile: val = relu(dinv*s + b), split bf16 hi/lo ----
    int tile = blockIdx.x;
#pragma unroll
    for (int ii = 0; ii < 8; ii++) {
        int idx = ii * 512 + t;              // 128*32 = 4096 items
        int r = idx >> 5, q = idx & 31;
        int m = tile * 128 + r;
        float4 v = make_float4(0.f, 0.f, 0.f, 0.f);
        float di = 0.f;
        if (m < NN) {
            v = __ldg((const float4*)in + (size_t)m * 32 + q);
            di = d_dinv[m];
        }
        float4 bb = __ldg((const float4*)bias + q);
        float a0 = fmaxf(fmaf(di, v.x, bb.x), 0.f);
        float a1 = fmaxf(fmaf(di, v.y, bb.y), 0.f);
        float a2 = fmaxf(fmaf(di, v.z, bb.z), 0.f);
        float a3 = fmaxf(fmaf(di, v.w, bb.w), 0.f);
        __nv_bfloat16 h0 = __float2bfloat16_rn(a0), h1 = __float2bfloat16_rn(a1);
        __nv_bfloat16 h2 = __float2bfloat16_rn(a2), h3 = __float2bfloat16_rn(a3);
        __nv_bfloat16 l0 = __float2bfloat16_rn(a0 - __bfloat162float(h0));
        __nv_bfloat16 l1 = __float2bfloat16_rn(a1 - __bfloat162float(h1));
        __nv_bfloat16 l2 = __float2bfloat16_rn(a2 - __bfloat162float(h2));
        __nv_bfloat16 l3 = __float2bfloat16_rn(a3 - __bfloat162float(h3));
        uint2 hp, lp;
        hp.x = (uint32_t)__bfloat16_as_ushort(h0) | ((uint32_t)__bfloat16_as_ushort(h1) << 16);
        hp.y = (uint32_t)__bfloat16_as_ushort(h2) | ((uint32_t)__bfloat16_as_ushort(h3) << 16);
        lp.x = (uint32_t)__bfloat16_as_ushort(l0) | ((uint32_t)__bfloat16_as_ushort(l1) << 16);
        lp.y = (uint32_t)__bfloat16_as_ushort(l2) | ((uint32_t)__bfloat16_as_ushort(l3) << 16);
        int off = (r * PITCH + q * 4) * 2;
        *(uint2*)(smb + A_HI + off) = hp;
        *(uint2*)(smb + A_LO + off) = lp;
    }
    __syncthreads();

    // ---- fragment addresses ----
    int rs = (w >> 1) * 16;          // 8 row strips of 16
    int cb = (w & 1) * 64;           // col half
    int arow = rs + (l & 7) + ((l >> 3) & 1) * 8;
    int acol8 = (l >> 4) * 8;
    uint32_t a_hi = sbase + A_HI + (arow * PITCH + acol8) * 2;
    uint32_t a_lo = sbase + A_LO + (arow * PITCH + acol8) * 2;
    int brow = (l & 7) + (l >> 4) * 8;
    int bk8  = ((l >> 3) & 1) * 8;

    float acc[32];
#pragma unroll
    for (int i = 0; i < 32; i++) acc[i] = 0.f;

#pragma unroll
    for (int kb = 0; kb < 8; kb++) {
        int k0 = kb * 16;
        uint32_t ah[4], al[4];
        LDM_X4(ah, a_hi + k0 * 2);
        LDM_X4(al, a_lo + k0 * 2);
#pragma unroll
        for (int np = 0; np < 4; np++) {
            int nb = cb + np * 16;
            uint32_t boff = (uint32_t)(((nb + brow) * PITCH + k0 + bk8) * 2);
            uint32_t bh[4], bl[4];
            LDM_X4(bh, sbase + B_HI + boff);
            LDM_X4(bl, sbase + B_LO + boff);
            float* c = acc + np * 8;
            mma_bf16(c,     ah, bh);
            mma_bf16(c,     ah, bl);
            mma_bf16(c,     al, bh);
            mma_bf16(c + 4, ah, bh + 2);
            mma_bf16(c + 4, ah, bl + 2);
            mma_bf16(c + 4, al, bh + 2);
        }
    }

    // ---- epilogue: scale rows by dinv, store fp32 ----
    int r0 = tile * 128 + rs + (l >> 2);
    int r1 = r0 + 8;
    float d0 = (r0 < NN) ? d_dinv[r0] : 0.f;
    float d1 = (r1 < NN) ? d_dinv[r1] : 0.f;
#pragma unroll
    for (int nt = 0; nt < 8; nt++) {
        int col = cb + nt * 8 + (l & 3) * 2;
        float* a = acc + nt * 4;
        if (r0 < NN) *(float2*)&out[(size_t)r0 * 128 + col] = make_float2(a[0] * d0, a[1] * d0);
        if (r1 < NN) *(float2*)&out[(size_t)r1 * 128 + col] = make_float2(a[2] * d1, a[3] * d1);
    }
}

// ---------------- fused gather + pooling --------------------------------------
__global__ void k_zero_pool() {
    int i = blockIdx.x * 256 + threadIdx.x;
    if (i < GG * 128) d_pool[i] = 0.f;
    if (i < GG) d_pcnt[i] = 0.f;
}
__global__ void k_gpool(const float* __restrict__ in, const int* __restrict__ batch,
                        const float* __restrict__ b3) {
    int v = blockIdx.x * 8 + (threadIdx.x >> 5);   // grid NN/8 exact
    int l = threadIdx.x & 31;
    float4 s = gather_row((const float4*)in, v, l);
    float di = __ldg(&d_dinv[v]);
    float4 bb = __ldg((const float4*)b3 + l);
    float4 o;
    o.x = fmaxf(fmaf(di, s.x, bb.x), 0.f);
    o.y = fmaxf(fmaf(di, s.y, bb.y), 0.f);
    o.z = fmaxf(fmaf(di, s.z, bb.z), 0.f);
    o.w = fmaxf(fmaf(di, s.w, bb.w), 0.f);
    int g = __ldg(&batch[v]);
    float* p = d_pool + g * 128 + l * 4;
    asm volatile("red.global.add.v4.f32 [%0], {%1,%2,%3,%4};"
                 :: "l"(p), "f"(o.x), "f"(o.y), "f"(o.z), "f"(o.w) : "memory");
    if (l == 0) atomicAdd(&d_pcnt[g], 1.0f);
}

// ---------------- final MLP ----------------------------------------------------
__global__ void k_mlp(const float* __restrict__ xs, const float* __restrict__ Wl1,
                      const float* __restrict__ bl1, const float* __restrict__ Wl2,
                      const float* __restrict__ bl2, float* __restrict__ out) {
    __shared__ float feat[132];
    __shared__ float part[64];
    int g = blockIdx.x, t = threadIdx.x;
    float inv = 1.0f / fmaxf(d_pcnt[g], 1.0f);
    for (int i = t; i < 132; i += 64)
        feat[i] = (i < 128) ? d_pool[g * 128 + i] * inv : xs[g * 4 + (i - 128)];
    __syncthreads();
    float h = bl1[t];
#pragma unroll 4
    for (int i = 0; i < 132; i++) h = fmaf(feat[i], Wl1[i * 64 + t], h);
    h = fmaxf(h, 0.f);
    part[t] = h * Wl2[t];
    __syncthreads();
    if (t == 0) {
        float s = bl2[0];
#pragma unroll
        for (int j = 0; j < 64; j++) s += part[j];
        out[g] = s;
    }
}

// ---------------- launcher ----------------------------------------------------
extern "C" void kernel_launch(void* const* d_in, const int* in_sizes, int n_in,
                              void* d_out, int out_size) {
    const float* x     = (const float*)d_in[0];
    const int*   ei    = (const int*)d_in[1];
    const float* xs    = (const float*)d_in[2];
    const int*   batch = (const int*)d_in[3];
    const float* W0  = (const float*)d_in[4];
    const float* b0  = (const float*)d_in[5];
    const float* W1  = (const float*)d_in[6];
    const float* b1  = (const float*)d_in[7];
    const float* W2  = (const float*)d_in[8];
    const float* b2  = (const float*)d_in[9];
    const float* W3  = (const float*)d_in[10];
    const float* b3  = (const float*)d_in[11];
    const float* Wl1 = (const float*)d_in[12];
    const float* bl1 = (const float*)d_in[13];
    const float* Wl2 = (const float*)d_in[14];
    const float* bl2 = (const float*)d_in[15];
    float* out = (float*)d_out;

    const int* srcp = ei;
    const int* dstp = ei + EE;

    cudaFuncSetAttribute(k_gemm_mma, cudaFuncAttributeMaxDynamicSharedMemorySize, SMEM_MMA);

    float *gp, *hp, *accp;
    cudaGetSymbolAddress((void**)&gp, d_g);
    cudaGetSymbolAddress((void**)&hp, d_h);
    cudaGetSymbolAddress((void**)&accp, d_acc);

    // degree + CSR build (reused by all 4 layers)
    k_zero_cnt<<<NB, 256>>>();
    k_count<<<(EE + 255) / 256, 256>>>(dstp);
    k_dinv<<<NB, 256>>>();
    k_scan1<<<NB, 256>>>();
    k_scan2<<<1, 512>>>();
    k_scan3<<<NB, 256>>>();
    k_fill<<<(EE + 255) / 256, 256>>>(srcp, dstp);

    // layer 0: p0 -> d_g
    k_gemm0<<<1024, 256>>>(x, W0);

    // layers 1..3: gather -> d_acc, GEMM -> ping-pong
    k_wconv<<<64, 256>>>(W1);
    k_gather<<<NN / 8, 256>>>(gp);
    k_gemm_mma<<<GT128, 512, SMEM_MMA>>>(accp, b0, hp);

    k_wconv<<<64, 256>>>(W2);
    k_gather<<<NN / 8, 256>>>(hp);
    k_gemm_mma<<<GT128, 512, SMEM_MMA>>>(accp, b1, gp);

    k_wconv<<<64, 256>>>(W3);
    k_gather<<<NN / 8, 256>>>(gp);
    k_gemm_mma<<<GT128, 512, SMEM_MMA>>>(accp, b2, hp);

    // fused gather + pool + head
    k_zero_pool<<<(GG * 128 + 255) / 256, 256>>>();
    k_gpool<<<NN / 8, 256>>>(hp, batch, b3);
    k_mlp<<<GG, 64>>>(xs, Wl1, bl1, Wl2, bl2, out);
}

// round 8
// speedup vs baseline: 1.3594x; 1.0523x over previous
#include <cuda_runtime.h>
#include <cuda_bf16.h>
#include <cstdint>

#define NN 100000
#define EE 600000
#define GG 1000
#define GT128 782    // ceil(NN/128)
#define NB 391       // ceil(NN/256)

// ---------------- static device scratch --------------------------------------
__device__ float d_dinv[NN];
__device__ float d_g[(size_t)NN * 128];      // ping (p fp32)
__device__ float d_h[(size_t)NN * 128];      // pong (p fp32)
__device__ uint32_t d_ahi[(size_t)NN * 64];  // A bf16 hi: 128 bf16 = 64 u32 per row
__device__ uint32_t d_alo[(size_t)NN * 64];  // A bf16 lo
__device__ float d_pool[GG * 128];
__device__ float d_pcnt[GG];
__device__ int   d_cnti[NN];
__device__ int   d_off[NN + 1];
__device__ int   d_cur[NN];
__device__ int   d_csr[EE];
__device__ int   d_bsum[NB + 1];
__device__ __nv_bfloat16 d_whi[3 * 128 * 128];   // W^T bf16 high, [layer][n][k]
__device__ __nv_bfloat16 d_wlo[3 * 128 * 128];   // W^T bf16 low

// ---------------- helpers ------------------------------------------------------
__device__ __forceinline__ uint32_t smem_u32(const void* p) {
    uint32_t a;
    asm("{ .reg .u64 t; cvta.to.shared.u64 t, %1; cvt.u32.u64 %0, t; }" : "=r"(a) : "l"(p));
    return a;
}
#define LDM_X4(r, addr) \
    asm volatile("ldmatrix.sync.aligned.m8n8.x4.shared.b16 {%0,%1,%2,%3}, [%4];" \
        : "=r"((r)[0]), "=r"((r)[1]), "=r"((r)[2]), "=r"((r)[3]) : "r"(addr))

__device__ __forceinline__ void mma_bf16(float* c, const uint32_t* a, const uint32_t* b) {
    asm volatile("mma.sync.aligned.m16n8k16.row.col.f32.bf16.bf16.f32 "
        "{%0,%1,%2,%3}, {%4,%5,%6,%7}, {%8,%9}, {%0,%1,%2,%3};"
        : "+f"(c[0]), "+f"(c[1]), "+f"(c[2]), "+f"(c[3])
        : "r"(a[0]), "r"(a[1]), "r"(a[2]), "r"(a[3]), "r"(b[0]), "r"(b[1]));
}

// CSR gather of one 128-float row (lane l owns float4 l), 2-way unrolled.
__device__ __forceinline__ float4 gather_row(const float4* __restrict__ P,
                                             int m, int l) {
    float4 a = __ldg(&P[(size_t)m * 32 + l]);
    int beg = __ldg(&d_off[m]), end = __ldg(&d_off[m + 1]);
    float4 a1 = make_float4(0.f, 0.f, 0.f, 0.f);
    int e = beg;
    for (; e + 1 < end; e += 2) {
        int s0 = __ldg(&d_csr[e]);
        int s1 = __ldg(&d_csr[e + 1]);
        float4 x0 = __ldg(&P[(size_t)s0 * 32 + l]);
        float4 x1 = __ldg(&P[(size_t)s1 * 32 + l]);
        a.x += x0.x; a.y += x0.y; a.z += x0.z; a.w += x0.w;
        a1.x += x1.x; a1.y += x1.y; a1.z += x1.z; a1.w += x1.w;
    }
    if (e < end) {
        int s0 = __ldg(&d_csr[e]);
        float4 x0 = __ldg(&P[(size_t)s0 * 32 + l]);
        a.x += x0.x; a.y += x0.y; a.z += x0.z; a.w += x0.w;
    }
    a.x += a1.x; a.y += a1.y; a.z += a1.z; a.w += a1.w;
    return a;
}

// ---------------- init / degree / CSR ------------------------------------------
__global__ void k_init() {     // zero cnt + pool + pcnt (500 blocks x 256)
    int i = blockIdx.x * 256 + threadIdx.x;
    if (i < NN) d_cnti[i] = 0;
    if (i < GG * 128) d_pool[i] = 0.f;
    if (i < GG) d_pcnt[i] = 0.f;
}
__global__ void k_count(const int* __restrict__ dst) {
    int e = blockIdx.x * 256 + threadIdx.x;
    if (e < EE) atomicAdd(&d_cnti[dst[e]], 1);
}
__global__ void k_scan1() {    // block scan + dinv
    __shared__ int s[256];
    int b = blockIdx.x, t = threadIdx.x;
    int i = b * 256 + t;
    int v = (i < NN) ? d_cnti[i] : 0;
    if (i < NN) d_dinv[i] = rsqrtf((float)(v + 1));
    s[t] = v;
    __syncthreads();
#pragma unroll
    for (int off = 1; off < 256; off <<= 1) {
        int x = (t >= off) ? s[t - off] : 0;
        __syncthreads();
        s[t] += x;
        __syncthreads();
    }
    if (i < NN) d_off[i] = s[t] - v;
    if (t == 255) d_bsum[b] = s[255];
}
__global__ void k_scan2() {   // 1 block, 512 threads
    __shared__ int s[512];
    int t = threadIdx.x;
    int v = (t < NB) ? d_bsum[t] : 0;
    s[t] = v;
    __syncthreads();
#pragma unroll
    for (int off = 1; off < 512; off <<= 1) {
        int x = (t >= off) ? s[t - off] : 0;
        __syncthreads();
        s[t] += x;
        __syncthreads();
    }
    if (t < NB) d_bsum[t] = s[t] - v;
}
__global__ void k_scan3() {
    int b = blockIdx.x, t = threadIdx.x;
    int i = b * 256 + t;
    if (i < NN) {
        int o = d_off[i] + d_bsum[b];
        d_off[i] = o;
        d_cur[i] = o;
    }
    if (i == 0) d_off[NN] = EE;
}
__global__ void k_fill(const int* __restrict__ src, const int* __restrict__ dst) {
    int e = blockIdx.x * 256 + threadIdx.x;
    if (e < EE) {
        int pos = atomicAdd(&d_cur[dst[e]], 1);
        d_csr[pos] = src[e];
    }
}

// ---------------- all W -> bf16 hi/lo, transposed [n][k] -----------------------
__global__ void k_wconv_all(const float* __restrict__ W1, const float* __restrict__ W2,
                            const float* __restrict__ W3) {
    int idx = blockIdx.x * 256 + threadIdx.x;   // 192 x 256 = 49152
    int layer = idx >> 14;
    int r = idx & 16383;
    const float* W = (layer == 0) ? W1 : (layer == 1) ? W2 : W3;
    int n = r & 127, k = r >> 7;
    float wv = __ldg(&W[k * 128 + n]);
    __nv_bfloat16 hb = __float2bfloat16_rn(wv);
    __nv_bfloat16 lb = __float2bfloat16_rn(wv - __bfloat162float(hb));
    d_whi[layer * 16384 + n * 128 + k] = hb;
    d_wlo[layer * 16384 + n * 128 + k] = lb;
}

// ---------------- layer 0: p0 = dinv * (x @ W0), K=4 --------------------------
__global__ void k_gemm0(const float* __restrict__ x, const float* __restrict__ W0) {
    int t = threadIdx.x;
    int j = t & 31;
    float w[16];
#pragma unroll
    for (int k = 0; k < 4; k++)
#pragma unroll
        for (int c = 0; c < 4; c++)
            w[k * 4 + c] = __ldg(&W0[k * 128 + j * 4 + c]);
    int gw = blockIdx.x * 8 + (t >> 5);
    for (int n = gw; n < NN; n += gridDim.x * 8) {
        float4 xv = __ldg((const float4*)x + n);
        float di = d_dinv[n];
        float4 r;
        r.x = di * (xv.x * w[0] + xv.y * w[4] + xv.z * w[8]  + xv.w * w[12]);
        r.y = di * (xv.x * w[1] + xv.y * w[5] + xv.z * w[9]  + xv.w * w[13]);
        r.z = di * (xv.x * w[2] + xv.y * w[6] + xv.z * w[10] + xv.w * w[14]);
        r.w = di * (xv.x * w[3] + xv.y * w[7] + xv.z * w[11] + xv.w * w[15]);
        ((float4*)d_g)[(size_t)n * 32 + j] = r;
    }
}

// ---- gather + transform + bf16 split: A[v] = bf16(relu(dinv*s + b)) ----------
__global__ void k_gatherA(const float* __restrict__ in, const float* __restrict__ bias) {
    int v = blockIdx.x * 8 + (threadIdx.x >> 5);   // grid NN/8, block 256
    int l = threadIdx.x & 31;
    float4 s = gather_row((const float4*)in, v, l);
    float di = __ldg(&d_dinv[v]);
    float4 bb = __ldg((const float4*)bias + l);
    float a0 = fmaxf(fmaf(di, s.x, bb.x), 0.f);
    float a1 = fmaxf(fmaf(di, s.y, bb.y), 0.f);
    float a2 = fmaxf(fmaf(di, s.z, bb.z), 0.f);
    float a3 = fmaxf(fmaf(di, s.w, bb.w), 0.f);
    __nv_bfloat16 h0 = __float2bfloat16_rn(a0), h1 = __float2bfloat16_rn(a1);
    __nv_bfloat16 h2 = __float2bfloat16_rn(a2), h3 = __float2bfloat16_rn(a3);
    __nv_bfloat16 l0 = __float2bfloat16_rn(a0 - __bfloat162float(h0));
    __nv_bfloat16 l1 = __float2bfloat16_rn(a1 - __bfloat162float(h1));
    __nv_bfloat16 l2 = __float2bfloat16_rn(a2 - __bfloat162float(h2));
    __nv_bfloat16 l3 = __float2bfloat16_rn(a3 - __bfloat162float(h3));
    uint2 hp, lp;
    hp.x = (uint32_t)__bfloat16_as_ushort(h0) | ((uint32_t)__bfloat16_as_ushort(h1) << 16);
    hp.y = (uint32_t)__bfloat16_as_ushort(h2) | ((uint32_t)__bfloat16_as_ushort(h3) << 16);
    lp.x = (uint32_t)__bfloat16_as_ushort(l0) | ((uint32_t)__bfloat16_as_ushort(l1) << 16);
    lp.y = (uint32_t)__bfloat16_as_ushort(l2) | ((uint32_t)__bfloat16_as_ushort(l3) << 16);
    ((uint2*)d_ahi)[(size_t)v * 32 + l] = hp;   // 32 uint2 = 256 B per row
    ((uint2*)d_alo)[(size_t)v * 32 + l] = lp;
}

// ---------------- HMMA GEMM: p = dinv * (A @ W) -------------------------------
// A pre-split bf16 in d_ahi/d_alo. 128x128 per block, 512 threads.
#define PITCH 136
#define A_HI 0
#define A_LO 34816
#define B_HI 69632
#define B_LO 104448
#define SMEM_MMA 139264

__global__ void __launch_bounds__(512) k_gemm_mma(int layer, float* __restrict__ out) {
    extern __shared__ char smb[];
    uint32_t sbase = smem_u32(smb);
    int t = threadIdx.x, w = t >> 5, l = t & 31;

    // ---- copy pre-converted W hi/lo into padded smem ----
    const uint4* WH = (const uint4*)(d_whi + layer * 16384);
    const uint4* WL = (const uint4*)(d_wlo + layer * 16384);
#pragma unroll
    for (int i = t; i < 2048; i += 512) {
        int n = i >> 4, k8 = (i & 15) * 8;
        int off = (n * PITCH + k8) * 2;
        *(uint4*)(smb + B_HI + off) = __ldg(&WH[i]);
        *(uint4*)(smb + B_LO + off) = __ldg(&WL[i]);
    }

    // ---- A tile: pure copy of pre-split bf16 (16 uint4 = 256 B per row) ----
    int tile = blockIdx.x;
    const uint4* AH = (const uint4*)d_ahi;
    const uint4* AL = (const uint4*)d_alo;
#pragma unroll
    for (int i = t; i < 2048; i += 512) {
        int r = i >> 4, j = i & 15;
        int m = tile * 128 + r;
        uint4 hv = make_uint4(0u, 0u, 0u, 0u), lv = hv;
        if (m < NN) {
            hv = __ldg(&AH[(size_t)m * 16 + j]);
            lv = __ldg(&AL[(size_t)m * 16 + j]);
        }
        int off = (r * PITCH + j * 8) * 2;
        *(uint4*)(smb + A_HI + off) = hv;
        *(uint4*)(smb + A_LO + off) = lv;
    }
    __syncthreads();

    // ---- fragment addresses ----
    int rs = (w >> 1) * 16;
    int cb = (w & 1) * 64;
    int arow = rs + (l & 7) + ((l >> 3) & 1) * 8;
    int acol8 = (l >> 4) * 8;
    uint32_t a_hi = sbase + A_HI + (arow * PITCH + acol8) * 2;
    uint32_t a_lo = sbase + A_LO + (arow * PITCH + acol8) * 2;
    int brow = (l & 7) + (l >> 4) * 8;
    int bk8  = ((l >> 3) & 1) * 8;

    float acc[32];
#pragma unroll
    for (int i = 0; i < 32; i++) acc[i] = 0.f;

#pragma unroll
    for (int kb = 0; kb < 8; kb++) {
        int k0 = kb * 16;
        uint32_t ah[4], al[4];
        LDM_X4(ah, a_hi + k0 * 2);
        LDM_X4(al, a_lo + k0 * 2);
#pragma unroll
        for (int np = 0; np < 4; np++) {
            int nb = cb + np * 16;
            uint32_t boff = (uint32_t)(((nb + brow) * PITCH + k0 + bk8) * 2);
            uint32_t bh[4], bl[4];
            LDM_X4(bh, sbase + B_HI + boff);
            LDM_X4(bl, sbase + B_LO + boff);
            float* c = acc + np * 8;
            mma_bf16(c,     ah, bh);
            mma_bf16(c,     ah, bl);
            mma_bf16(c,     al, bh);
            mma_bf16(c + 4, ah, bh + 2);
            mma_bf16(c + 4, ah, bl + 2);
            mma_bf16(c + 4, al, bh + 2);
        }
    }

    // ---- epilogue: scale rows by dinv, store fp32 p ----
    int r0 = tile * 128 + rs + (l >> 2);
    int r1 = r0 + 8;
    float d0 = (r0 < NN) ? d_dinv[r0] : 0.f;
    float d1 = (r1 < NN) ? d_dinv[r1] : 0.f;
#pragma unroll
    for (int nt = 0; nt < 8; nt++) {
        int col = cb + nt * 8 + (l & 3) * 2;
        float* a = acc + nt * 4;
        if (r0 < NN) *(float2*)&out[(size_t)r0 * 128 + col] = make_float2(a[0] * d0, a[1] * d0);
        if (r1 < NN) *(float2*)&out[(size_t)r1 * 128 + col] = make_float2(a[2] * d1, a[3] * d1);
    }
}

// ---------------- fused gather + pooling --------------------------------------
__global__ void k_gpool(const float* __restrict__ in, const int* __restrict__ batch,
                        const float* __restrict__ b3) {
    int v = blockIdx.x * 8 + (threadIdx.x >> 5);   // grid NN/8 exact
    int l = threadIdx.x & 31;
    float4 s = gather_row((const float4*)in, v, l);
    float di = __ldg(&d_dinv[v]);
    float4 bb = __ldg((const float4*)b3 + l);
    float4 o;
    o.x = fmaxf(fmaf(di, s.x, bb.x), 0.f);
    o.y = fmaxf(fmaf(di, s.y, bb.y), 0.f);
    o.z = fmaxf(fmaf(di, s.z, bb.z), 0.f);
    o.w = fmaxf(fmaf(di, s.w, bb.w), 0.f);
    int g = __ldg(&batch[v]);
    float* p = d_pool + g * 128 + l * 4;
    asm volatile("red.global.add.v4.f32 [%0], {%1,%2,%3,%4};"
                 :: "l"(p), "f"(o.x), "f"(o.y), "f"(o.z), "f"(o.w) : "memory");
    if (l == 0) atomicAdd(&d_pcnt[g], 1.0f);
}

// ---------------- final MLP ----------------------------------------------------
__global__ void k_mlp(const float* __restrict__ xs, const float* __restrict__ Wl1,
                      const float* __restrict__ bl1, const float* __restrict__ Wl2,
                      const float* __restrict__ bl2, float* __restrict__ out) {
    __shared__ float feat[132];
    __shared__ float part[64];
    int g = blockIdx.x, t = threadIdx.x;
    float inv = 1.0f / fmaxf(d_pcnt[g], 1.0f);
    for (int i = t; i < 132; i += 64)
        feat[i] = (i < 128) ? d_pool[g * 128 + i] * inv : xs[g * 4 + (i - 128)];
    __syncthreads();
    float h = bl1[t];
#pragma unroll 4
    for (int i = 0; i < 132; i++) h = fmaf(feat[i], Wl1[i * 64 + t], h);
    h = fmaxf(h, 0.f);
    part[t] = h * Wl2[t];
    __syncthreads();
    if (t == 0) {
        float s = bl2[0];
#pragma unroll
        for (int j = 0; j < 64; j++) s += part[j];
        out[g] = s;
    }
}

// ---------------- launcher ----------------------------------------------------
extern "C" void kernel_launch(void* const* d_in, const int* in_sizes, int n_in,
                              void* d_out, int out_size) {
    const float* x     = (const float*)d_in[0];
    const int*   ei    = (const int*)d_in[1];
    const float* xs    = (const float*)d_in[2];
    const int*   batch = (const int*)d_in[3];
    const float* W0  = (const float*)d_in[4];
    const float* b0  = (const float*)d_in[5];
    const float* W1  = (const float*)d_in[6];
    const float* b1  = (const float*)d_in[7];
    const float* W2  = (const float*)d_in[8];
    const float* b2  = (const float*)d_in[9];
    const float* W3  = (const float*)d_in[10];
    const float* b3  = (const float*)d_in[11];
    const float* Wl1 = (const float*)d_in[12];
    const float* bl1 = (const float*)d_in[13];
    const float* Wl2 = (const float*)d_in[14];
    const float* bl2 = (const float*)d_in[15];
    float* out = (float*)d_out;

    const int* srcp = ei;
    const int* dstp = ei + EE;

    cudaFuncSetAttribute(k_gemm_mma, cudaFuncAttributeMaxDynamicSharedMemorySize, SMEM_MMA);

    float *gp, *hp;
    cudaGetSymbolAddress((void**)&gp, d_g);
    cudaGetSymbolAddress((void**)&hp, d_h);

    // init + degree + CSR build
    k_init<<<500, 256>>>();
    k_count<<<(EE + 255) / 256, 256>>>(dstp);
    k_scan1<<<NB, 256>>>();
    k_scan2<<<1, 512>>>();
    k_scan3<<<NB, 256>>>();
    k_fill<<<(EE + 255) / 256, 256>>>(srcp, dstp);
    k_wconv_all<<<192, 256>>>(W1, W2, W3);

    // layer 0: p0 -> d_g
    k_gemm0<<<1024, 256>>>(x, W0);

    // layers 1..3: gather+transform -> bf16 A, GEMM -> p (ping-pong)
    k_gatherA<<<NN / 8, 256>>>(gp, b0);
    k_gemm_mma<<<GT128, 512, SMEM_MMA>>>(0, hp);

    k_gatherA<<<NN / 8, 256>>>(hp, b1);
    k_gemm_mma<<<GT128, 512, SMEM_MMA>>>(1, gp);

    k_gatherA<<<NN / 8, 256>>>(gp, b2);
    k_gemm_mma<<<GT128, 512, SMEM_MMA>>>(2, hp);

    // fused gather + pool + head
    k_gpool<<<NN / 8, 256>>>(hp, batch, b3);
    k_mlp<<<GG, 64>>>(xs, Wl1, bl1, Wl2, bl2, out);
}

// round 9
// speedup vs baseline: 1.3871x; 1.0204x over previous
#include <cuda_runtime.h>
#include <cuda_bf16.h>
#include <cstdint>

#define NN 100000
#define EE 600000
#define GG 1000
#define GT128 782    // ceil(NN/128)
#define NB 391       // ceil(NN/256)
#define NSM 148

// ---------------- static device scratch --------------------------------------
__device__ float d_dinv[NN];
__device__ float d_g[(size_t)NN * 128];      // ping (p fp32)
__device__ float d_h[(size_t)NN * 128];      // pong (p fp32)
__device__ uint32_t d_ahi[(size_t)NN * 64];  // A bf16 hi: 128 bf16 = 64 u32 per row
__device__ uint32_t d_alo[(size_t)NN * 64];  // A bf16 lo
__device__ float d_pool[GG * 128];
__device__ float d_pcnt[GG];
__device__ int   d_cnti[NN];
__device__ int   d_off[NN + 1];
__device__ int   d_cur[NN];
__device__ int   d_csr[EE];
__device__ int   d_bsum[NB + 1];
__device__ __nv_bfloat16 d_whi[3 * 128 * 128];   // W^T bf16 high, [layer][n][k]
__device__ __nv_bfloat16 d_wlo[3 * 128 * 128];   // W^T bf16 low

// ---------------- helpers ------------------------------------------------------
__device__ __forceinline__ uint32_t smem_u32(const void* p) {
    uint32_t a;
    asm("{ .reg .u64 t; cvta.to.shared.u64 t, %1; cvt.u32.u64 %0, t; }" : "=r"(a) : "l"(p));
    return a;
}
#define LDM_X4(r, addr) \
    asm volatile("ldmatrix.sync.aligned.m8n8.x4.shared.b16 {%0,%1,%2,%3}, [%4];" \
        : "=r"((r)[0]), "=r"((r)[1]), "=r"((r)[2]), "=r"((r)[3]) : "r"(addr))

__device__ __forceinline__ void mma_bf16(float* c, const uint32_t* a, const uint32_t* b) {
    asm volatile("mma.sync.aligned.m16n8k16.row.col.f32.bf16.bf16.f32 "
        "{%0,%1,%2,%3}, {%4,%5,%6,%7}, {%8,%9}, {%0,%1,%2,%3};"
        : "+f"(c[0]), "+f"(c[1]), "+f"(c[2]), "+f"(c[3])
        : "r"(a[0]), "r"(a[1]), "r"(a[2]), "r"(a[3]), "r"(b[0]), "r"(b[1]));
}

// CSR gather of one 128-float row (lane l owns float4 l), 2-way unrolled.
__device__ __forceinline__ float4 gather_row(const float4* __restrict__ P,
                                             int m, int l) {
    float4 a = __ldg(&P[(size_t)m * 32 + l]);
    int beg = __ldg(&d_off[m]), end = __ldg(&d_off[m + 1]);
    float4 a1 = make_float4(0.f, 0.f, 0.f, 0.f);
    int e = beg;
    for (; e + 1 < end; e += 2) {
        int s0 = __ldg(&d_csr[e]);
        int s1 = __ldg(&d_csr[e + 1]);
        float4 x0 = __ldg(&P[(size_t)s0 * 32 + l]);
        float4 x1 = __ldg(&P[(size_t)s1 * 32 + l]);
        a.x += x0.x; a.y += x0.y; a.z += x0.z; a.w += x0.w;
        a1.x += x1.x; a1.y += x1.y; a1.z += x1.z; a1.w += x1.w;
    }
    if (e < end) {
        int s0 = __ldg(&d_csr[e]);
        float4 x0 = __ldg(&P[(size_t)s0 * 32 + l]);
        a.x += x0.x; a.y += x0.y; a.z += x0.z; a.w += x0.w;
    }
    a.x += a1.x; a.y += a1.y; a.z += a1.z; a.w += a1.w;
    return a;
}

// ---------------- init / degree / CSR ------------------------------------------
__global__ void k_init() {     // zero cnt + pool + pcnt (500 blocks x 256)
    int i = blockIdx.x * 256 + threadIdx.x;
    if (i < NN) d_cnti[i] = 0;
    if (i < GG * 128) d_pool[i] = 0.f;
    if (i < GG) d_pcnt[i] = 0.f;
}
__global__ void k_count(const int* __restrict__ dst) {
    int e = blockIdx.x * 256 + threadIdx.x;
    if (e < EE) atomicAdd(&d_cnti[dst[e]], 1);
}
__global__ void k_scan1() {    // block scan + dinv
    __shared__ int s[256];
    int b = blockIdx.x, t = threadIdx.x;
    int i = b * 256 + t;
    int v = (i < NN) ? d_cnti[i] : 0;
    if (i < NN) d_dinv[i] = rsqrtf((float)(v + 1));
    s[t] = v;
    __syncthreads();
#pragma unroll
    for (int off = 1; off < 256; off <<= 1) {
        int x = (t >= off) ? s[t - off] : 0;
        __syncthreads();
        s[t] += x;
        __syncthreads();
    }
    if (i < NN) d_off[i] = s[t] - v;
    if (t == 255) d_bsum[b] = s[255];
}
__global__ void k_scan2() {   // 1 block, 512 threads
    __shared__ int s[512];
    int t = threadIdx.x;
    int v = (t < NB) ? d_bsum[t] : 0;
    s[t] = v;
    __syncthreads();
#pragma unroll
    for (int off = 1; off < 512; off <<= 1) {
        int x = (t >= off) ? s[t - off] : 0;
        __syncthreads();
        s[t] += x;
        __syncthreads();
    }
    if (t < NB) d_bsum[t] = s[t] - v;
}
__global__ void k_scan3() {
    int b = blockIdx.x, t = threadIdx.x;
    int i = b * 256 + t;
    if (i < NN) {
        int o = d_off[i] + d_bsum[b];
        d_off[i] = o;
        d_cur[i] = o;
    }
    if (i == 0) d_off[NN] = EE;
}
__global__ void k_fill(const int* __restrict__ src, const int* __restrict__ dst) {
    int e = blockIdx.x * 256 + threadIdx.x;
    if (e < EE) {
        int pos = atomicAdd(&d_cur[dst[e]], 1);
        d_csr[pos] = src[e];
    }
}

// ---------------- all W -> bf16 hi/lo, transposed [n][k] -----------------------
__global__ void k_wconv_all(const float* __restrict__ W1, const float* __restrict__ W2,
                            const float* __restrict__ W3) {
    int idx = blockIdx.x * 256 + threadIdx.x;   // 192 x 256 = 49152
    int layer = idx >> 14;
    int r = idx & 16383;
    const float* W = (layer == 0) ? W1 : (layer == 1) ? W2 : W3;
    int n = r & 127, k = r >> 7;
    float wv = __ldg(&W[k * 128 + n]);
    __nv_bfloat16 hb = __float2bfloat16_rn(wv);
    __nv_bfloat16 lb = __float2bfloat16_rn(wv - __bfloat162float(hb));
    d_whi[layer * 16384 + n * 128 + k] = hb;
    d_wlo[layer * 16384 + n * 128 + k] = lb;
}

// ---------------- layer 0: p0 = dinv * (x @ W0), K=4 --------------------------
__global__ void k_gemm0(const float* __restrict__ x, const float* __restrict__ W0) {
    int t = threadIdx.x;
    int j = t & 31;
    float w[16];
#pragma unroll
    for (int k = 0; k < 4; k++)
#pragma unroll
        for (int c = 0; c < 4; c++)
            w[k * 4 + c] = __ldg(&W0[k * 128 + j * 4 + c]);
    int gw = blockIdx.x * 8 + (t >> 5);
    for (int n = gw; n < NN; n += gridDim.x * 8) {
        float4 xv = __ldg((const float4*)x + n);
        float di = d_dinv[n];
        float4 r;
        r.x = di * (xv.x * w[0] + xv.y * w[4] + xv.z * w[8]  + xv.w * w[12]);
        r.y = di * (xv.x * w[1] + xv.y * w[5] + xv.z * w[9]  + xv.w * w[13]);
        r.z = di * (xv.x * w[2] + xv.y * w[6] + xv.z * w[10] + xv.w * w[14]);
        r.w = di * (xv.x * w[3] + xv.y * w[7] + xv.z * w[11] + xv.w * w[15]);
        ((float4*)d_g)[(size_t)n * 32 + j] = r;
    }
}

// ---- gather + transform + bf16 split: A[v] = bf16(relu(dinv*s + b)) ----------
__global__ void k_gatherA(const float* __restrict__ in, const float* __restrict__ bias) {
    int v = blockIdx.x * 8 + (threadIdx.x >> 5);   // grid NN/8, block 256
    int l = threadIdx.x & 31;
    float4 s = gather_row((const float4*)in, v, l);
    float di = __ldg(&d_dinv[v]);
    float4 bb = __ldg((const float4*)bias + l);
    float a0 = fmaxf(fmaf(di, s.x, bb.x), 0.f);
    float a1 = fmaxf(fmaf(di, s.y, bb.y), 0.f);
    float a2 = fmaxf(fmaf(di, s.z, bb.z), 0.f);
    float a3 = fmaxf(fmaf(di, s.w, bb.w), 0.f);
    __nv_bfloat16 h0 = __float2bfloat16_rn(a0), h1 = __float2bfloat16_rn(a1);
    __nv_bfloat16 h2 = __float2bfloat16_rn(a2), h3 = __float2bfloat16_rn(a3);
    __nv_bfloat16 l0 = __float2bfloat16_rn(a0 - __bfloat162float(h0));
    __nv_bfloat16 l1 = __float2bfloat16_rn(a1 - __bfloat162float(h1));
    __nv_bfloat16 l2 = __float2bfloat16_rn(a2 - __bfloat162float(h2));
    __nv_bfloat16 l3 = __float2bfloat16_rn(a3 - __bfloat162float(h3));
    uint2 hp, lp;
    hp.x = (uint32_t)__bfloat16_as_ushort(h0) | ((uint32_t)__bfloat16_as_ushort(h1) << 16);
    hp.y = (uint32_t)__bfloat16_as_ushort(h2) | ((uint32_t)__bfloat16_as_ushort(h3) << 16);
    lp.x = (uint32_t)__bfloat16_as_ushort(l0) | ((uint32_t)__bfloat16_as_ushort(l1) << 16);
    lp.y = (uint32_t)__bfloat16_as_ushort(l2) | ((uint32_t)__bfloat16_as_ushort(l3) << 16);
    ((uint2*)d_ahi)[(size_t)v * 32 + l] = hp;
    ((uint2*)d_alo)[(size_t)v * 32 + l] = lp;
}

// ---------------- persistent HMMA GEMM: p = dinv * (A @ W) --------------------
// Grid = NSM. W loaded into smem once per CTA; loop over tiles stride gridDim.
#define PITCH 136
#define A_HI 0
#define A_LO 34816
#define B_HI 69632
#define B_LO 104448
#define SMEM_MMA 139264

__global__ void __launch_bounds__(512) k_gemm_mma(int layer, float* __restrict__ out) {
    extern __shared__ char smb[];
    uint32_t sbase = smem_u32(smb);
    int t = threadIdx.x, w = t >> 5, l = t & 31;

    // ---- copy pre-converted W hi/lo into padded smem (once) ----
    const uint4* WH = (const uint4*)(d_whi + layer * 16384);
    const uint4* WL = (const uint4*)(d_wlo + layer * 16384);
#pragma unroll
    for (int i = t; i < 2048; i += 512) {
        int n = i >> 4, k8 = (i & 15) * 8;
        int off = (n * PITCH + k8) * 2;
        *(uint4*)(smb + B_HI + off) = __ldg(&WH[i]);
        *(uint4*)(smb + B_LO + off) = __ldg(&WL[i]);
    }

    // ---- per-warp constant fragment addressing ----
    int rs = (w >> 1) * 16;
    int cb = (w & 1) * 64;
    int arow = rs + (l & 7) + ((l >> 3) & 1) * 8;
    int acol8 = (l >> 4) * 8;
    uint32_t a_hi_base = sbase + A_HI + (arow * PITCH + acol8) * 2;
    uint32_t a_lo_base = sbase + A_LO + (arow * PITCH + acol8) * 2;
    int brow = (l & 7) + (l >> 4) * 8;
    int bk8  = ((l >> 3) & 1) * 8;

    const uint4* AH = (const uint4*)d_ahi;
    const uint4* AL = (const uint4*)d_alo;

    for (int tile = blockIdx.x; tile < GT128; tile += gridDim.x) {
        __syncthreads();   // previous iteration's MMA reads done before overwrite

        // ---- A tile: pure copy of pre-split bf16 (16 uint4 = 256 B per row) ----
#pragma unroll
        for (int i = t; i < 2048; i += 512) {
            int r = i >> 4, j = i & 15;
            int m = tile * 128 + r;
            uint4 hv = make_uint4(0u, 0u, 0u, 0u), lv = hv;
            if (m < NN) {
                hv = __ldg(&AH[(size_t)m * 16 + j]);
                lv = __ldg(&AL[(size_t)m * 16 + j]);
            }
            int off = (r * PITCH + j * 8) * 2;
            *(uint4*)(smb + A_HI + off) = hv;
            *(uint4*)(smb + A_LO + off) = lv;
        }
        __syncthreads();

        float acc[32];
#pragma unroll
        for (int i = 0; i < 32; i++) acc[i] = 0.f;

#pragma unroll
        for (int kb = 0; kb < 8; kb++) {
            int k0 = kb * 16;
            uint32_t ah[4], al[4];
            LDM_X4(ah, a_hi_base + k0 * 2);
            LDM_X4(al, a_lo_base + k0 * 2);
#pragma unroll
            for (int np = 0; np < 4; np++) {
                int nb = cb + np * 16;
                uint32_t boff = (uint32_t)(((nb + brow) * PITCH + k0 + bk8) * 2);
                uint32_t bh[4], bl[4];
                LDM_X4(bh, sbase + B_HI + boff);
                LDM_X4(bl, sbase + B_LO + boff);
                float* c = acc + np * 8;
                mma_bf16(c,     ah, bh);
                mma_bf16(c,     ah, bl);
                mma_bf16(c,     al, bh);
                mma_bf16(c + 4, ah, bh + 2);
                mma_bf16(c + 4, ah, bl + 2);
                mma_bf16(c + 4, al, bh + 2);
            }
        }

        // ---- epilogue: scale rows by dinv, store fp32 p ----
        int r0 = tile * 128 + rs + (l >> 2);
        int r1 = r0 + 8;
        float d0 = (r0 < NN) ? d_dinv[r0] : 0.f;
        float d1 = (r1 < NN) ? d_dinv[r1] : 0.f;
#pragma unroll
        for (int nt = 0; nt < 8; nt++) {
            int col = cb + nt * 8 + (l & 3) * 2;
            float* a = acc + nt * 4;
            if (r0 < NN) *(float2*)&out[(size_t)r0 * 128 + col] = make_float2(a[0] * d0, a[1] * d0);
            if (r1 < NN) *(float2*)&out[(size_t)r1 * 128 + col] = make_float2(a[2] * d1, a[3] * d1);
        }
    }
}

// ---------------- fused gather + pooling --------------------------------------
__global__ void k_gpool(const float* __restrict__ in, const int* __restrict__ batch,
                        const float* __restrict__ b3) {
    int v = blockIdx.x * 8 + (threadIdx.x >> 5);   // grid NN/8 exact
    int l = threadIdx.x & 31;
    float4 s = gather_row((const float4*)in, v, l);
    float di = __ldg(&d_dinv[v]);
    float4 bb = __ldg((const float4*)b3 + l);
    float4 o;
    o.x = fmaxf(fmaf(di, s.x, bb.x), 0.f);
    o.y = fmaxf(fmaf(di, s.y, bb.y), 0.f);
    o.z = fmaxf(fmaf(di, s.z, bb.z), 0.f);
    o.w = fmaxf(fmaf(di, s.w, bb.w), 0.f);
    int g = __ldg(&batch[v]);
    float* p = d_pool + g * 128 + l * 4;
    asm volatile("red.global.add.v4.f32 [%0], {%1,%2,%3,%4};"
                 :: "l"(p), "f"(o.x), "f"(o.y), "f"(o.z), "f"(o.w) : "memory");
    if (l == 0) atomicAdd(&d_pcnt[g], 1.0f);
}

// ---------------- final MLP ----------------------------------------------------
__global__ void k_mlp(const float* __restrict__ xs, const float* __restrict__ Wl1,
                      const float* __restrict__ bl1, const float* __restrict__ Wl2,
                      const float* __restrict__ bl2, float* __restrict__ out) {
    __shared__ float feat[132];
    __shared__ float part[64];
    int g = blockIdx.x, t = threadIdx.x;
    float inv = 1.0f / fmaxf(d_pcnt[g], 1.0f);
    for (int i = t; i < 132; i += 64)
        feat[i] = (i < 128) ? d_pool[g * 128 + i] * inv : xs[g * 4 + (i - 128)];
    __syncthreads();
    float h = bl1[t];
#pragma unroll 4
    for (int i = 0; i < 132; i++) h = fmaf(feat[i], Wl1[i * 64 + t], h);
    h = fmaxf(h, 0.f);
    part[t] = h * Wl2[t];
    __syncthreads();
    if (t == 0) {
        float s = bl2[0];
#pragma unroll
        for (int j = 0; j < 64; j++) s += part[j];
        out[g] = s;
    }
}

// ---------------- launcher ----------------------------------------------------
extern "C" void kernel_launch(void* const* d_in, const int* in_sizes, int n_in,
                              void* d_out, int out_size) {
    const float* x     = (const float*)d_in[0];
    const int*   ei    = (const int*)d_in[1];
    const float* xs    = (const float*)d_in[2];
    const int*   batch = (const int*)d_in[3];
    const float* W0  = (const float*)d_in[4];
    const float* b0  = (const float*)d_in[5];
    const float* W1  = (const float*)d_in[6];
    const float* b1  = (const float*)d_in[7];
    const float* W2  = (const float*)d_in[8];
    const float* b2  = (const float*)d_in[9];
    const float* W3  = (const float*)d_in[10];
    const float* b3  = (const float*)d_in[11];
    const float* Wl1 = (const float*)d_in[12];
    const float* bl1 = (const float*)d_in[13];
    const float* Wl2 = (const float*)d_in[14];
    const float* bl2 = (const float*)d_in[15];
    float* out = (float*)d_out;

    const int* srcp = ei;
    const int* dstp = ei + EE;

    cudaFuncSetAttribute(k_gemm_mma, cudaFuncAttributeMaxDynamicSharedMemorySize, SMEM_MMA);

    float *gp, *hp;
    cudaGetSymbolAddress((void**)&gp, d_g);
    cudaGetSymbolAddress((void**)&hp, d_h);

    // init + degree + CSR build
    k_init<<<500, 256>>>();
    k_count<<<(EE + 255) / 256, 256>>>(dstp);
    k_scan1<<<NB, 256>>>();
    k_scan2<<<1, 512>>>();
    k_scan3<<<NB, 256>>>();
    k_fill<<<(EE + 255) / 256, 256>>>(srcp, dstp);
    k_wconv_all<<<192, 256>>>(W1, W2, W3);

    // layer 0: p0 -> d_g
    k_gemm0<<<1024, 256>>>(x, W0);

    // layers 1..3: gather+transform -> bf16 A, persistent GEMM -> p (ping-pong)
    k_gatherA<<<NN / 8, 256>>>(gp, b0);
    k_gemm_mma<<<NSM, 512, SMEM_MMA>>>(0, hp);

    k_gatherA<<<NN / 8, 256>>>(hp, b1);
    k_gemm_mma<<<NSM, 512, SMEM_MMA>>>(1, gp);

    k_gatherA<<<NN / 8, 256>>>(gp, b2);
    k_gemm_mma<<<NSM, 512, SMEM_MMA>>>(2, hp);

    // fused gather + pool + head
    k_gpool<<<NN / 8, 256>>>(hp, batch, b3);
    k_mlp<<<GG, 64>>>(xs, Wl1, bl1, Wl2, bl2, out);
}

// round 10
// speedup vs baseline: 1.5799x; 1.1390x over previous
#include <cuda_runtime.h>
#include <cuda_bf16.h>
#include <cstdint>

#define NN 100000
#define EE 600000
#define GG 1000
#define GT128 782    // ceil(NN/128)
#define NB 391       // ceil(NN/256)
#define NSM 148

// ---------------- static device scratch --------------------------------------
__device__ float d_dinv[NN];
__device__ uint32_t d_g[(size_t)NN * 64];    // ping: p packed bf16x2 (128 bf16/row)
__device__ uint32_t d_h[(size_t)NN * 64];    // pong
__device__ uint32_t d_ahi[(size_t)NN * 64];  // A bf16 hi (packed x2)
__device__ uint32_t d_alo[(size_t)NN * 64];  // A bf16 lo
__device__ float d_pool[GG * 128];
__device__ float d_pcnt[GG];
__device__ int   d_cnti[NN];
__device__ int   d_off[NN + 1];
__device__ int   d_cur[NN];
__device__ int   d_csr[EE];
__device__ int   d_bsum[NB + 1];
__device__ __nv_bfloat16 d_whi[3 * 128 * 128];   // W^T bf16 high, [layer][n][k]
__device__ __nv_bfloat16 d_wlo[3 * 128 * 128];   // W^T bf16 low

// ---------------- helpers ------------------------------------------------------
__device__ __forceinline__ uint32_t smem_u32(const void* p) {
    uint32_t a;
    asm("{ .reg .u64 t; cvta.to.shared.u64 t, %1; cvt.u32.u64 %0, t; }" : "=r"(a) : "l"(p));
    return a;
}
#define LDM_X4(r, addr) \
    asm volatile("ldmatrix.sync.aligned.m8n8.x4.shared.b16 {%0,%1,%2,%3}, [%4];" \
        : "=r"((r)[0]), "=r"((r)[1]), "=r"((r)[2]), "=r"((r)[3]) : "r"(addr))

__device__ __forceinline__ void mma_bf16(float* c, const uint32_t* a, const uint32_t* b) {
    asm volatile("mma.sync.aligned.m16n8k16.row.col.f32.bf16.bf16.f32 "
        "{%0,%1,%2,%3}, {%4,%5,%6,%7}, {%8,%9}, {%0,%1,%2,%3};"
        : "+f"(c[0]), "+f"(c[1]), "+f"(c[2]), "+f"(c[3])
        : "r"(a[0]), "r"(a[1]), "r"(a[2]), "r"(a[3]), "r"(b[0]), "r"(b[1]));
}

__device__ __forceinline__ uint32_t pkbf(float a, float b) {
    __nv_bfloat162 t = __floats2bfloat162_rn(a, b);   // x=a (low), y=b (high)
    return *(uint32_t*)&t;
}
__device__ __forceinline__ float4 b2f(uint2 u) {
    float2 f0 = __bfloat1622float2(*(__nv_bfloat162*)&u.x);
    float2 f1 = __bfloat1622float2(*(__nv_bfloat162*)&u.y);
    return make_float4(f0.x, f0.y, f1.x, f1.y);
}

// CSR gather of one 128-value bf16 row (lane l owns cols 4l..4l+3), fp32 accum.
__device__ __forceinline__ float4 gather_row_bf(const uint2* __restrict__ P,
                                                int m, int l) {
    float4 a = b2f(__ldg(&P[(size_t)m * 32 + l]));
    int beg = __ldg(&d_off[m]), end = __ldg(&d_off[m + 1]);
    float4 a1 = make_float4(0.f, 0.f, 0.f, 0.f);
    int e = beg;
    for (; e + 1 < end; e += 2) {
        int s0 = __ldg(&d_csr[e]);
        int s1 = __ldg(&d_csr[e + 1]);
        float4 x0 = b2f(__ldg(&P[(size_t)s0 * 32 + l]));
        float4 x1 = b2f(__ldg(&P[(size_t)s1 * 32 + l]));
        a.x += x0.x; a.y += x0.y; a.z += x0.z; a.w += x0.w;
        a1.x += x1.x; a1.y += x1.y; a1.z += x1.z; a1.w += x1.w;
    }
    if (e < end) {
        int s0 = __ldg(&d_csr[e]);
        float4 x0 = b2f(__ldg(&P[(size_t)s0 * 32 + l]));
        a.x += x0.x; a.y += x0.y; a.z += x0.z; a.w += x0.w;
    }
    a.x += a1.x; a.y += a1.y; a.z += a1.z; a.w += a1.w;
    return a;
}

// ---------------- init / degree / CSR ------------------------------------------
__global__ void k_init() {     // zero cnt + pool + pcnt (500 blocks x 256)
    int i = blockIdx.x * 256 + threadIdx.x;
    if (i < NN) d_cnti[i] = 0;
    if (i < GG * 128) d_pool[i] = 0.f;
    if (i < GG) d_pcnt[i] = 0.f;
}
__global__ void k_count(const int* __restrict__ dst) {
    int e = blockIdx.x * 256 + threadIdx.x;
    if (e < EE) atomicAdd(&d_cnti[dst[e]], 1);
}
__global__ void k_scan1() {    // block scan + dinv
    __shared__ int s[256];
    int b = blockIdx.x, t = threadIdx.x;
    int i = b * 256 + t;
    int v = (i < NN) ? d_cnti[i] : 0;
    if (i < NN) d_dinv[i] = rsqrtf((float)(v + 1));
    s[t] = v;
    __syncthreads();
#pragma unroll
    for (int off = 1; off < 256; off <<= 1) {
        int x = (t >= off) ? s[t - off] : 0;
        __syncthreads();
        s[t] += x;
        __syncthreads();
    }
    if (i < NN) d_off[i] = s[t] - v;
    if (t == 255) d_bsum[b] = s[255];
}
__global__ void k_scan2() {   // 1 block, 512 threads
    __shared__ int s[512];
    int t = threadIdx.x;
    int v = (t < NB) ? d_bsum[t] : 0;
    s[t] = v;
    __syncthreads();
#pragma unroll
    for (int off = 1; off < 512; off <<= 1) {
        int x = (t >= off) ? s[t - off] : 0;
        __syncthreads();
        s[t] += x;
        __syncthreads();
    }
    if (t < NB) d_bsum[t] = s[t] - v;
}
__global__ void k_scan3() {
    int b = blockIdx.x, t = threadIdx.x;
    int i = b * 256 + t;
    if (i < NN) {
        int o = d_off[i] + d_bsum[b];
        d_off[i] = o;
        d_cur[i] = o;
    }
    if (i == 0) d_off[NN] = EE;
}
__global__ void k_fill(const int* __restrict__ src, const int* __restrict__ dst) {
    int e = blockIdx.x * 256 + threadIdx.x;
    if (e < EE) {
        int pos = atomicAdd(&d_cur[dst[e]], 1);
        d_csr[pos] = src[e];
    }
}

// ---------------- all W -> bf16 hi/lo, transposed [n][k] -----------------------
__global__ void k_wconv_all(const float* __restrict__ W1, const float* __restrict__ W2,
                            const float* __restrict__ W3) {
    int idx = blockIdx.x * 256 + threadIdx.x;   // 192 x 256 = 49152
    int layer = idx >> 14;
    int r = idx & 16383;
    const float* W = (layer == 0) ? W1 : (layer == 1) ? W2 : W3;
    int n = r & 127, k = r >> 7;
    float wv = __ldg(&W[k * 128 + n]);
    __nv_bfloat16 hb = __float2bfloat16_rn(wv);
    __nv_bfloat16 lb = __float2bfloat16_rn(wv - __bfloat162float(hb));
    d_whi[layer * 16384 + n * 128 + k] = hb;
    d_wlo[layer * 16384 + n * 128 + k] = lb;
}

// ---------------- layer 0: p0 = bf16(dinv * (x @ W0)), K=4 --------------------
__global__ void k_gemm0(const float* __restrict__ x, const float* __restrict__ W0) {
    int t = threadIdx.x;
    int j = t & 31;
    float w[16];
#pragma unroll
    for (int k = 0; k < 4; k++)
#pragma unroll
        for (int c = 0; c < 4; c++)
            w[k * 4 + c] = __ldg(&W0[k * 128 + j * 4 + c]);
    int gw = blockIdx.x * 8 + (t >> 5);
    for (int n = gw; n < NN; n += gridDim.x * 8) {
        float4 xv = __ldg((const float4*)x + n);
        float di = d_dinv[n];
        float4 r;
        r.x = di * (xv.x * w[0] + xv.y * w[4] + xv.z * w[8]  + xv.w * w[12]);
        r.y = di * (xv.x * w[1] + xv.y * w[5] + xv.z * w[9]  + xv.w * w[13]);
        r.z = di * (xv.x * w[2] + xv.y * w[6] + xv.z * w[10] + xv.w * w[14]);
        r.w = di * (xv.x * w[3] + xv.y * w[7] + xv.z * w[11] + xv.w * w[15]);
        ((uint2*)d_g)[(size_t)n * 32 + j] = make_uint2(pkbf(r.x, r.y), pkbf(r.z, r.w));
    }
}

// ---- gather + transform + bf16 split: A[v] = bf16(relu(dinv*s + b)) ----------
__global__ void k_gatherA(const uint32_t* __restrict__ in, const float* __restrict__ bias) {
    int v = blockIdx.x * 8 + (threadIdx.x >> 5);   // grid NN/8, block 256
    int l = threadIdx.x & 31;
    float4 s = gather_row_bf((const uint2*)in, v, l);
    float di = __ldg(&d_dinv[v]);
    float4 bb = __ldg((const float4*)bias + l);
    float a0 = fmaxf(fmaf(di, s.x, bb.x), 0.f);
    float a1 = fmaxf(fmaf(di, s.y, bb.y), 0.f);
    float a2 = fmaxf(fmaf(di, s.z, bb.z), 0.f);
    float a3 = fmaxf(fmaf(di, s.w, bb.w), 0.f);
    __nv_bfloat16 h0 = __float2bfloat16_rn(a0), h1 = __float2bfloat16_rn(a1);
    __nv_bfloat16 h2 = __float2bfloat16_rn(a2), h3 = __float2bfloat16_rn(a3);
    __nv_bfloat16 l0 = __float2bfloat16_rn(a0 - __bfloat162float(h0));
    __nv_bfloat16 l1 = __float2bfloat16_rn(a1 - __bfloat162float(h1));
    __nv_bfloat16 l2 = __float2bfloat16_rn(a2 - __bfloat162float(h2));
    __nv_bfloat16 l3 = __float2bfloat16_rn(a3 - __bfloat162float(h3));
    uint2 hp, lp;
    hp.x = (uint32_t)__bfloat16_as_ushort(h0) | ((uint32_t)__bfloat16_as_ushort(h1) << 16);
    hp.y = (uint32_t)__bfloat16_as_ushort(h2) | ((uint32_t)__bfloat16_as_ushort(h3) << 16);
    lp.x = (uint32_t)__bfloat16_as_ushort(l0) | ((uint32_t)__bfloat16_as_ushort(l1) << 16);
    lp.y = (uint32_t)__bfloat16_as_ushort(l2) | ((uint32_t)__bfloat16_as_ushort(l3) << 16);
    ((uint2*)d_ahi)[(size_t)v * 32 + l] = hp;
    ((uint2*)d_alo)[(size_t)v * 32 + l] = lp;
}

// ---------------- persistent HMMA GEMM: p = bf16(dinv * (A @ W)) --------------
#define PITCH 136
#define A_HI 0
#define A_LO 34816
#define B_HI 69632
#define B_LO 104448
#define SMEM_MMA 139264

__global__ void __launch_bounds__(512) k_gemm_mma(int layer, uint32_t* __restrict__ out) {
    extern __shared__ char smb[];
    uint32_t sbase = smem_u32(smb);
    int t = threadIdx.x, w = t >> 5, l = t & 31;

    // ---- copy pre-converted W hi/lo into padded smem (once) ----
    const uint4* WH = (const uint4*)(d_whi + layer * 16384);
    const uint4* WL = (const uint4*)(d_wlo + layer * 16384);
#pragma unroll
    for (int i = t; i < 2048; i += 512) {
        int n = i >> 4, k8 = (i & 15) * 8;
        int off = (n * PITCH + k8) * 2;
        *(uint4*)(smb + B_HI + off) = __ldg(&WH[i]);
        *(uint4*)(smb + B_LO + off) = __ldg(&WL[i]);
    }

    // ---- per-warp constant fragment addressing ----
    int rs = (w >> 1) * 16;
    int cb = (w & 1) * 64;
    int arow = rs + (l & 7) + ((l >> 3) & 1) * 8;
    int acol8 = (l >> 4) * 8;
    uint32_t a_hi_base = sbase + A_HI + (arow * PITCH + acol8) * 2;
    uint32_t a_lo_base = sbase + A_LO + (arow * PITCH + acol8) * 2;
    int brow = (l & 7) + (l >> 4) * 8;
    int bk8  = ((l >> 3) & 1) * 8;

    const uint4* AH = (const uint4*)d_ahi;
    const uint4* AL = (const uint4*)d_alo;

    for (int tile = blockIdx.x; tile < GT128; tile += gridDim.x) {
        __syncthreads();   // previous iteration's MMA reads done before overwrite

        // ---- A tile: pure copy of pre-split bf16 (16 uint4 = 256 B per row) ----
#pragma unroll
        for (int i = t; i < 2048; i += 512) {
            int r = i >> 4, j = i & 15;
            int m = tile * 128 + r;
            uint4 hv = make_uint4(0u, 0u, 0u, 0u), lv = hv;
            if (m < NN) {
                hv = __ldg(&AH[(size_t)m * 16 + j]);
                lv = __ldg(&AL[(size_t)m * 16 + j]);
            }
            int off = (r * PITCH + j * 8) * 2;
            *(uint4*)(smb + A_HI + off) = hv;
            *(uint4*)(smb + A_LO + off) = lv;
        }
        __syncthreads();

        float acc[32];
#pragma unroll
        for (int i = 0; i < 32; i++) acc[i] = 0.f;

#pragma unroll
        for (int kb = 0; kb < 8; kb++) {
            int k0 = kb * 16;
            uint32_t ah[4], al[4];
            LDM_X4(ah, a_hi_base + k0 * 2);
            LDM_X4(al, a_lo_base + k0 * 2);
#pragma unroll
            for (int np = 0; np < 4; np++) {
                int nb = cb + np * 16;
                uint32_t boff = (uint32_t)(((nb + brow) * PITCH + k0 + bk8) * 2);
                uint32_t bh[4], bl[4];
                LDM_X4(bh, sbase + B_HI + boff);
                LDM_X4(bl, sbase + B_LO + boff);
                float* c = acc + np * 8;
                mma_bf16(c,     ah, bh);
                mma_bf16(c,     ah, bl);
                mma_bf16(c,     al, bh);
                mma_bf16(c + 4, ah, bh + 2);
                mma_bf16(c + 4, ah, bl + 2);
                mma_bf16(c + 4, al, bh + 2);
            }
        }

        // ---- epilogue: scale rows by dinv, store packed bf16 p ----
        int r0 = tile * 128 + rs + (l >> 2);
        int r1 = r0 + 8;
        float d0 = (r0 < NN) ? d_dinv[r0] : 0.f;
        float d1 = (r1 < NN) ? d_dinv[r1] : 0.f;
#pragma unroll
        for (int nt = 0; nt < 8; nt++) {
            int col = cb + nt * 8 + (l & 3) * 2;
            float* a = acc + nt * 4;
            if (r0 < NN) out[(size_t)r0 * 64 + (col >> 1)] = pkbf(a[0] * d0, a[1] * d0);
            if (r1 < NN) out[(size_t)r1 * 64 + (col >> 1)] = pkbf(a[2] * d1, a[3] * d1);
        }
    }
}

// ---------------- fused gather + pooling --------------------------------------
__global__ void k_gpool(const uint32_t* __restrict__ in, const int* __restrict__ batch,
                        const float* __restrict__ b3) {
    int v = blockIdx.x * 8 + (threadIdx.x >> 5);   // grid NN/8 exact
    int l = threadIdx.x & 31;
    float4 s = gather_row_bf((const uint2*)in, v, l);
    float di = __ldg(&d_dinv[v]);
    float4 bb = __ldg((const float4*)b3 + l);
    float4 o;
    o.x = fmaxf(fmaf(di, s.x, bb.x), 0.f);
    o.y = fmaxf(fmaf(di, s.y, bb.y), 0.f);
    o.z = fmaxf(fmaf(di, s.z, bb.z), 0.f);
    o.w = fmaxf(fmaf(di, s.w, bb.w), 0.f);
    int g = __ldg(&batch[v]);
    float* p = d_pool + g * 128 + l * 4;
    asm volatile("red.global.add.v4.f32 [%0], {%1,%2,%3,%4};"
                 :: "l"(p), "f"(o.x), "f"(o.y), "f"(o.z), "f"(o.w) : "memory");
    if (l == 0) atomicAdd(&d_pcnt[g], 1.0f);
}

// ---------------- final MLP ----------------------------------------------------
__global__ void k_mlp(const float* __restrict__ xs, const float* __restrict__ Wl1,
                      const float* __restrict__ bl1, const float* __restrict__ Wl2,
                      const float* __restrict__ bl2, float* __restrict__ out) {
    __shared__ float feat[132];
    __shared__ float part[64];
    int g = blockIdx.x, t = threadIdx.x;
    float inv = 1.0f / fmaxf(d_pcnt[g], 1.0f);
    for (int i = t; i < 132; i += 64)
        feat[i] = (i < 128) ? d_pool[g * 128 + i] * inv : xs[g * 4 + (i - 128)];
    __syncthreads();
    float h = bl1[t];
#pragma unroll 4
    for (int i = 0; i < 132; i++) h = fmaf(feat[i], Wl1[i * 64 + t], h);
    h = fmaxf(h, 0.f);
    part[t] = h * Wl2[t];
    __syncthreads();
    if (t == 0) {
        float s = bl2[0];
#pragma unroll
        for (int j = 0; j < 64; j++) s += part[j];
        out[g] = s;
    }
}

// ---------------- launcher ----------------------------------------------------
extern "C" void kernel_launch(void* const* d_in, const int* in_sizes, int n_in,
                              void* d_out, int out_size) {
    const float* x     = (const float*)d_in[0];
    const int*   ei    = (const int*)d_in[1];
    const float* xs    = (const float*)d_in[2];
    const int*   batch = (const int*)d_in[3];
    const float* W0  = (const float*)d_in[4];
    const float* b0  = (const float*)d_in[5];
    const float* W1  = (const float*)d_in[6];
    const float* b1  = (const float*)d_in[7];
    const float* W2  = (const float*)d_in[8];
    const float* b2  = (const float*)d_in[9];
    const float* W3  = (const float*)d_in[10];
    const float* b3  = (const float*)d_in[11];
    const float* Wl1 = (const float*)d_in[12];
    const float* bl1 = (const float*)d_in[13];
    const float* Wl2 = (const float*)d_in[14];
    const float* bl2 = (const float*)d_in[15];
    float* out = (float*)d_out;

    const int* srcp = ei;
    const int* dstp = ei + EE;

    cudaFuncSetAttribute(k_gemm_mma, cudaFuncAttributeMaxDynamicSharedMemorySize, SMEM_MMA);

    uint32_t *gp, *hp;
    cudaGetSymbolAddress((void**)&gp, d_g);
    cudaGetSymbolAddress((void**)&hp, d_h);

    // init + degree + CSR build
    k_init<<<500, 256>>>();
    k_count<<<(EE + 255) / 256, 256>>>(dstp);
    k_scan1<<<NB, 256>>>();
    k_scan2<<<1, 512>>>();
    k_scan3<<<NB, 256>>>();
    k_fill<<<(EE + 255) / 256, 256>>>(srcp, dstp);
    k_wconv_all<<<192, 256>>>(W1, W2, W3);

    // layer 0: p0 -> d_g (bf16)
    k_gemm0<<<1024, 256>>>(x, W0);

    // layers 1..3: gather+transform -> bf16 A, persistent GEMM -> bf16 p
    k_gatherA<<<NN / 8, 256>>>(gp, b0);
    k_gemm_mma<<<NSM, 512, SMEM_MMA>>>(0, hp);

    k_gatherA<<<NN / 8, 256>>>(hp, b1);
    k_gemm_mma<<<NSM, 512, SMEM_MMA>>>(1, gp);

    k_gatherA<<<NN / 8, 256>>>(gp, b2);
    k_gemm_mma<<<NSM, 512, SMEM_MMA>>>(2, hp);

    // fused gather + pool + head
    k_gpool<<<NN / 8, 256>>>(hp, batch, b3);
    k_mlp<<<GG, 64>>>(xs, Wl1, bl1, Wl2, bl2, out);
}

// round 11
// speedup vs baseline: 1.8595x; 1.1770x over previous
#include <cuda_runtime.h>
#include <cuda_bf16.h>
#include <cstdint>

#define NN 100000
#define EE 600000
#define GG 1000
#define GT128 782    // ceil(NN/128)
#define NB 391       // ceil(NN/256)
#define NSM 148

// ---------------- static device scratch --------------------------------------
__device__ float d_dinv[NN];
__device__ uint32_t d_g[(size_t)NN * 64];    // ping: p packed bf16x2 (128 bf16/row)
__device__ uint32_t d_h[(size_t)NN * 64];    // pong
__device__ uint32_t d_ahi[(size_t)NN * 64];  // A packed bf16 (single precision level)
__device__ float d_pool[GG * 128];
__device__ float d_pcnt[GG];
__device__ int   d_cnti[NN];
__device__ int   d_off[NN + 1];
__device__ int   d_cur[NN];
__device__ int   d_csr[EE];
__device__ int   d_bsum[NB + 1];
__device__ __nv_bfloat16 d_whi[3 * 128 * 128];   // W^T bf16 high, [layer][n][k]
__device__ __nv_bfloat16 d_wlo[3 * 128 * 128];   // W^T bf16 low

// ---------------- helpers ------------------------------------------------------
__device__ __forceinline__ uint32_t smem_u32(const void* p) {
    uint32_t a;
    asm("{ .reg .u64 t; cvta.to.shared.u64 t, %1; cvt.u32.u64 %0, t; }" : "=r"(a) : "l"(p));
    return a;
}
#define LDM_X4(r, addr) \
    asm volatile("ldmatrix.sync.aligned.m8n8.x4.shared.b16 {%0,%1,%2,%3}, [%4];" \
        : "=r"((r)[0]), "=r"((r)[1]), "=r"((r)[2]), "=r"((r)[3]) : "r"(addr))

__device__ __forceinline__ void mma_bf16(float* c, const uint32_t* a, const uint32_t* b) {
    asm volatile("mma.sync.aligned.m16n8k16.row.col.f32.bf16.bf16.f32 "
        "{%0,%1,%2,%3}, {%4,%5,%6,%7}, {%8,%9}, {%0,%1,%2,%3};"
        : "+f"(c[0]), "+f"(c[1]), "+f"(c[2]), "+f"(c[3])
        : "r"(a[0]), "r"(a[1]), "r"(a[2]), "r"(a[3]), "r"(b[0]), "r"(b[1]));
}

__device__ __forceinline__ uint32_t pkbf(float a, float b) {
    __nv_bfloat162 t = __floats2bfloat162_rn(a, b);
    return *(uint32_t*)&t;
}
__device__ __forceinline__ float4 b2f(uint2 u) {
    float2 f0 = __bfloat1622float2(*(__nv_bfloat162*)&u.x);
    float2 f1 = __bfloat1622float2(*(__nv_bfloat162*)&u.y);
    return make_float4(f0.x, f0.y, f1.x, f1.y);
}

// CSR gather of one 128-value bf16 row (lane l owns cols 4l..4l+3), fp32 accum.
__device__ __forceinline__ float4 gather_row_bf(const uint2* __restrict__ P,
                                                int m, int l) {
    float4 a = b2f(__ldg(&P[(size_t)m * 32 + l]));
    int beg = __ldg(&d_off[m]), end = __ldg(&d_off[m + 1]);
    float4 a1 = make_float4(0.f, 0.f, 0.f, 0.f);
    int e = beg;
    for (; e + 1 < end; e += 2) {
        int s0 = __ldg(&d_csr[e]);
        int s1 = __ldg(&d_csr[e + 1]);
        float4 x0 = b2f(__ldg(&P[(size_t)s0 * 32 + l]));
        float4 x1 = b2f(__ldg(&P[(size_t)s1 * 32 + l]));
        a.x += x0.x; a.y += x0.y; a.z += x0.z; a.w += x0.w;
        a1.x += x1.x; a1.y += x1.y; a1.z += x1.z; a1.w += x1.w;
    }
    if (e < end) {
        int s0 = __ldg(&d_csr[e]);
        float4 x0 = b2f(__ldg(&P[(size_t)s0 * 32 + l]));
        a.x += x0.x; a.y += x0.y; a.z += x0.z; a.w += x0.w;
    }
    a.x += a1.x; a.y += a1.y; a.z += a1.z; a.w += a1.w;
    return a;
}

// ---------------- init / degree / CSR ------------------------------------------
__global__ void k_init() {
    int i = blockIdx.x * 256 + threadIdx.x;
    if (i < NN) d_cnti[i] = 0;
    if (i < GG * 128) d_pool[i] = 0.f;
    if (i < GG) d_pcnt[i] = 0.f;
}
__global__ void k_count(const int* __restrict__ dst) {
    int e = blockIdx.x * 256 + threadIdx.x;
    if (e < EE) atomicAdd(&d_cnti[dst[e]], 1);
}
__global__ void k_scan1() {
    __shared__ int s[256];
    int b = blockIdx.x, t = threadIdx.x;
    int i = b * 256 + t;
    int v = (i < NN) ? d_cnti[i] : 0;
    if (i < NN) d_dinv[i] = rsqrtf((float)(v + 1));
    s[t] = v;
    __syncthreads();
#pragma unroll
    for (int off = 1; off < 256; off <<= 1) {
        int x = (t >= off) ? s[t - off] : 0;
        __syncthreads();
        s[t] += x;
        __syncthreads();
    }
    if (i < NN) d_off[i] = s[t] - v;
    if (t == 255) d_bsum[b] = s[255];
}
__global__ void k_scan2() {
    __shared__ int s[512];
    int t = threadIdx.x;
    int v = (t < NB) ? d_bsum[t] : 0;
    s[t] = v;
    __syncthreads();
#pragma unroll
    for (int off = 1; off < 512; off <<= 1) {
        int x = (t >= off) ? s[t - off] : 0;
        __syncthreads();
        s[t] += x;
        __syncthreads();
    }
    if (t < NB) d_bsum[t] = s[t] - v;
}
__global__ void k_scan3() {
    int b = blockIdx.x, t = threadIdx.x;
    int i = b * 256 + t;
    if (i < NN) {
        int o = d_off[i] + d_bsum[b];
        d_off[i] = o;
        d_cur[i] = o;
    }
    if (i == 0) d_off[NN] = EE;
}
__global__ void k_fill(const int* __restrict__ src, const int* __restrict__ dst) {
    int e = blockIdx.x * 256 + threadIdx.x;
    if (e < EE) {
        int pos = atomicAdd(&d_cur[dst[e]], 1);
        d_csr[pos] = src[e];
    }
}

// ---------------- all W -> bf16 hi/lo, transposed [n][k] -----------------------
__global__ void k_wconv_all(const float* __restrict__ W1, const float* __restrict__ W2,
                            const float* __restrict__ W3) {
    int idx = blockIdx.x * 256 + threadIdx.x;
    int layer = idx >> 14;
    int r = idx & 16383;
    const float* W = (layer == 0) ? W1 : (layer == 1) ? W2 : W3;
    int n = r & 127, k = r >> 7;
    float wv = __ldg(&W[k * 128 + n]);
    __nv_bfloat16 hb = __float2bfloat16_rn(wv);
    __nv_bfloat16 lb = __float2bfloat16_rn(wv - __bfloat162float(hb));
    d_whi[layer * 16384 + n * 128 + k] = hb;
    d_wlo[layer * 16384 + n * 128 + k] = lb;
}

// ---------------- layer 0: p0 = bf16(dinv * (x @ W0)), K=4 --------------------
__global__ void k_gemm0(const float* __restrict__ x, const float* __restrict__ W0) {
    int t = threadIdx.x;
    int j = t & 31;
    float w[16];
#pragma unroll
    for (int k = 0; k < 4; k++)
#pragma unroll
        for (int c = 0; c < 4; c++)
            w[k * 4 + c] = __ldg(&W0[k * 128 + j * 4 + c]);
    int gw = blockIdx.x * 8 + (t >> 5);
    for (int n = gw; n < NN; n += gridDim.x * 8) {
        float4 xv = __ldg((const float4*)x + n);
        float di = d_dinv[n];
        float4 r;
        r.x = di * (xv.x * w[0] + xv.y * w[4] + xv.z * w[8]  + xv.w * w[12]);
        r.y = di * (xv.x * w[1] + xv.y * w[5] + xv.z * w[9]  + xv.w * w[13]);
        r.z = di * (xv.x * w[2] + xv.y * w[6] + xv.z * w[10] + xv.w * w[14]);
        r.w = di * (xv.x * w[3] + xv.y * w[7] + xv.z * w[11] + xv.w * w[15]);
        ((uint2*)d_g)[(size_t)n * 32 + j] = make_uint2(pkbf(r.x, r.y), pkbf(r.z, r.w));
    }
}

// ---- gather + transform: A[v] = bf16(relu(dinv*s + b)) ------------------------
__global__ void k_gatherA(const uint32_t* __restrict__ in, const float* __restrict__ bias) {
    int v = blockIdx.x * 8 + (threadIdx.x >> 5);   // grid NN/8, block 256
    int l = threadIdx.x & 31;
    float4 s = gather_row_bf((const uint2*)in, v, l);
    float di = __ldg(&d_dinv[v]);
    float4 bb = __ldg((const float4*)bias + l);
    float a0 = fmaxf(fmaf(di, s.x, bb.x), 0.f);
    float a1 = fmaxf(fmaf(di, s.y, bb.y), 0.f);
    float a2 = fmaxf(fmaf(di, s.z, bb.z), 0.f);
    float a3 = fmaxf(fmaf(di, s.w, bb.w), 0.f);
    ((uint2*)d_ahi)[(size_t)v * 32 + l] = make_uint2(pkbf(a0, a1), pkbf(a2, a3));
}

// ---------------- persistent HMMA GEMM: p = bf16(dinv * (A @ W)) --------------
// A single bf16 (2 products: A*Whi + A*Wlo). Double-buffered A via cp.async.
#define PITCH 136
#define A_BUF0 0
#define A_BUF1 34816
#define B_HI 69632
#define B_LO 104448
#define SMEM_MMA 139264

__global__ void __launch_bounds__(512) k_gemm_mma(int layer, uint32_t* __restrict__ out) {
    extern __shared__ char smb[];
    uint32_t sbase = smem_u32(smb);
    int t = threadIdx.x, w = t >> 5, l = t & 31;

    const uint4* AH = (const uint4*)d_ahi;
    int tile0 = blockIdx.x;

    // ---- prologue: async-load A(tile0) into buf0 ----
    {
        int m128 = tile0 * 128;
#pragma unroll
        for (int i = t; i < 2048; i += 512) {
            int r = i >> 4, j = i & 15;
            int m = m128 + r;
            int mc = (m < NN) ? m : (NN - 1);
            int pb = (m < NN) ? 16 : 0;
            uint32_t dst = sbase + A_BUF0 + (uint32_t)((r * PITCH + j * 8) * 2);
            asm volatile("cp.async.cg.shared.global [%0], [%1], 16, %2;"
                         :: "r"(dst), "l"(&AH[(size_t)mc * 16 + j]), "r"(pb));
        }
        asm volatile("cp.async.commit_group;" ::: "memory");
    }

    // ---- W hi/lo into smem (once) ----
    const uint4* WH = (const uint4*)(d_whi + layer * 16384);
    const uint4* WL = (const uint4*)(d_wlo + layer * 16384);
#pragma unroll
    for (int i = t; i < 2048; i += 512) {
        int n = i >> 4, k8 = (i & 15) * 8;
        int off = (n * PITCH + k8) * 2;
        *(uint4*)(smb + B_HI + off) = __ldg(&WH[i]);
        *(uint4*)(smb + B_LO + off) = __ldg(&WL[i]);
    }
    asm volatile("cp.async.wait_group 0;" ::: "memory");
    __syncthreads();

    // ---- per-warp constant fragment addressing ----
    int rs = (w >> 1) * 16;
    int cb = (w & 1) * 64;
    int arow = rs + (l & 7) + ((l >> 3) & 1) * 8;
    int acol8 = (l >> 4) * 8;
    uint32_t a_frag = sbase + (uint32_t)((arow * PITCH + acol8) * 2);
    int brow = (l & 7) + (l >> 4) * 8;
    int bk8  = ((l >> 3) & 1) * 8;

    int par = 0;
    for (int tile = tile0; tile < GT128; tile += gridDim.x, par ^= 1) {
        // ---- prefetch next A tile into the other buffer ----
        int next = tile + gridDim.x;
        if (next < GT128) {
            int m128 = next * 128;
            uint32_t boff = (par == 0) ? A_BUF1 : A_BUF0;
#pragma unroll
            for (int i = t; i < 2048; i += 512) {
                int r = i >> 4, j = i & 15;
                int m = m128 + r;
                int mc = (m < NN) ? m : (NN - 1);
                int pb = (m < NN) ? 16 : 0;
                uint32_t dst = sbase + boff + (uint32_t)((r * PITCH + j * 8) * 2);
                asm volatile("cp.async.cg.shared.global [%0], [%1], 16, %2;"
                             :: "r"(dst), "l"(&AH[(size_t)mc * 16 + j]), "r"(pb));
            }
            asm volatile("cp.async.commit_group;" ::: "memory");
        }

        // ---- MMA on current buffer ----
        uint32_t a_base = a_frag + (par ? A_BUF1 : A_BUF0);
        float acc[32];
#pragma unroll
        for (int i = 0; i < 32; i++) acc[i] = 0.f;

#pragma unroll
        for (int kb = 0; kb < 8; kb++) {
            int k0 = kb * 16;
            uint32_t ah[4];
            LDM_X4(ah, a_base + k0 * 2);
#pragma unroll
            for (int np = 0; np < 4; np++) {
                int nb = cb + np * 16;
                uint32_t boff2 = (uint32_t)(((nb + brow) * PITCH + k0 + bk8) * 2);
                uint32_t bh[4], bl[4];
                LDM_X4(bh, sbase + B_HI + boff2);
                LDM_X4(bl, sbase + B_LO + boff2);
                float* c = acc + np * 8;
                mma_bf16(c,     ah, bh);
                mma_bf16(c,     ah, bl);
                mma_bf16(c + 4, ah, bh + 2);
                mma_bf16(c + 4, ah, bl + 2);
            }
        }

        // ---- epilogue: scale rows by dinv, store packed bf16 p ----
        int r0 = tile * 128 + rs + (l >> 2);
        int r1 = r0 + 8;
        float d0 = (r0 < NN) ? d_dinv[r0] : 0.f;
        float d1 = (r1 < NN) ? d_dinv[r1] : 0.f;
#pragma unroll
        for (int nt = 0; nt < 8; nt++) {
            int col = cb + nt * 8 + (l & 3) * 2;
            float* a = acc + nt * 4;
            if (r0 < NN) out[(size_t)r0 * 64 + (col >> 1)] = pkbf(a[0] * d0, a[1] * d0);
            if (r1 < NN) out[(size_t)r1 * 64 + (col >> 1)] = pkbf(a[2] * d1, a[3] * d1);
        }

        if (next < GT128)
            asm volatile("cp.async.wait_group 0;" ::: "memory");
        __syncthreads();
    }
}

// ---------------- fused gather + pooling --------------------------------------
__global__ void k_gpool(const uint32_t* __restrict__ in, const int* __restrict__ batch,
                        const float* __restrict__ b3) {
    int v = blockIdx.x * 8 + (threadIdx.x >> 5);   // grid NN/8 exact
    int l = threadIdx.x & 31;
    float4 s = gather_row_bf((const uint2*)in, v, l);
    float di = __ldg(&d_dinv[v]);
    float4 bb = __ldg((const float4*)b3 + l);
    float4 o;
    o.x = fmaxf(fmaf(di, s.x, bb.x), 0.f);
    o.y = fmaxf(fmaf(di, s.y, bb.y), 0.f);
    o.z = fmaxf(fmaf(di, s.z, bb.z), 0.f);
    o.w = fmaxf(fmaf(di, s.w, bb.w), 0.f);
    int g = __ldg(&batch[v]);
    float* p = d_pool + g * 128 + l * 4;
    asm volatile("red.global.add.v4.f32 [%0], {%1,%2,%3,%4};"
                 :: "l"(p), "f"(o.x), "f"(o.y), "f"(o.z), "f"(o.w) : "memory");
    if (l == 0) atomicAdd(&d_pcnt[g], 1.0f);
}

// ---------------- final MLP ----------------------------------------------------
__global__ void k_mlp(const float* __restrict__ xs, const float* __restrict__ Wl1,
                      const float* __restrict__ bl1, const float* __restrict__ Wl2,
                      const float* __restrict__ bl2, float* __restrict__ out) {
    __shared__ float feat[132];
    __shared__ float part[64];
    int g = blockIdx.x, t = threadIdx.x;
    float inv = 1.0f / fmaxf(d_pcnt[g], 1.0f);
    for (int i = t; i < 132; i += 64)
        feat[i] = (i < 128) ? d_pool[g * 128 + i] * inv : xs[g * 4 + (i - 128)];
    __syncthreads();
    float h = bl1[t];
#pragma unroll 4
    for (int i = 0; i < 132; i++) h = fmaf(feat[i], Wl1[i * 64 + t], h);
    h = fmaxf(h, 0.f);
    part[t] = h * Wl2[t];
    __syncthreads();
    if (t == 0) {
        float s = bl2[0];
#pragma unroll
        for (int j = 0; j < 64; j++) s += part[j];
        out[g] = s;
    }
}

// ---------------- launcher ----------------------------------------------------
extern "C" void kernel_launch(void* const* d_in, const int* in_sizes, int n_in,
                              void* d_out, int out_size) {
    const float* x     = (const float*)d_in[0];
    const int*   ei    = (const int*)d_in[1];
    const float* xs    = (const float*)d_in[2];
    const int*   batch = (const int*)d_in[3];
    const float* W0  = (const float*)d_in[4];
    const float* b0  = (const float*)d_in[5];
    const float* W1  = (const float*)d_in[6];
    const float* b1  = (const float*)d_in[7];
    const float* W2  = (const float*)d_in[8];
    const float* b2  = (const float*)d_in[9];
    const float* W3  = (const float*)d_in[10];
    const float* b3  = (const float*)d_in[11];
    const float* Wl1 = (const float*)d_in[12];
    const float* bl1 = (const float*)d_in[13];
    const float* Wl2 = (const float*)d_in[14];
    const float* bl2 = (const float*)d_in[15];
    float* out = (float*)d_out;

    const int* srcp = ei;
    const int* dstp = ei + EE;

    cudaFuncSetAttribute(k_gemm_mma, cudaFuncAttributeMaxDynamicSharedMemorySize, SMEM_MMA);

    uint32_t *gp, *hp;
    cudaGetSymbolAddress((void**)&gp, d_g);
    cudaGetSymbolAddress((void**)&hp, d_h);

    // init + degree + CSR build
    k_init<<<500, 256>>>();
    k_count<<<(EE + 255) / 256, 256>>>(dstp);
    k_scan1<<<NB, 256>>>();
    k_scan2<<<1, 512>>>();
    k_scan3<<<NB, 256>>>();
    k_fill<<<(EE + 255) / 256, 256>>>(srcp, dstp);
    k_wconv_all<<<192, 256>>>(W1, W2, W3);

    // layer 0: p0 -> d_g (bf16)
    k_gemm0<<<1024, 256>>>(x, W0);

    // layers 1..3: gather+transform -> bf16 A, pipelined persistent GEMM
    k_gatherA<<<NN / 8, 256>>>(gp, b0);
    k_gemm_mma<<<NSM, 512, SMEM_MMA>>>(0, hp);

    k_gatherA<<<NN / 8, 256>>>(hp, b1);
    k_gemm_mma<<<NSM, 512, SMEM_MMA>>>(1, gp);

    k_gatherA<<<NN / 8, 256>>>(gp, b2);
    k_gemm_mma<<<NSM, 512, SMEM_MMA>>>(2, hp);

    // fused gather + pool + head
    k_gpool<<<NN / 8, 256>>>(hp, batch, b3);
    k_mlp<<<GG, 64>>>(xs, Wl1, bl1, Wl2, bl2, out);
}